// round 1
// baseline (speedup 1.0000x reference)
#include <cuda_runtime.h>
#include <math.h>

#define BB   8
#define NN   9216      // 96*96
#define KK   256       // all projections have K=256 input channels

// ---------------- scratch (static device allocations are allowed) -------------
__device__ float g_q  [(size_t)BB * 256 * NN];   // (b, h*32+d, n)
__device__ float g_kv [(size_t)BB * 512 * NN];   // (b, h*64 + {0:k,32:v}+d, n)
__device__ float g_Rq [(size_t)BB * 512 * NN];   // (b, h*64+r, n) after softmax
__device__ float g_Rk [(size_t)BB * 512 * NN];
__device__ float g_tok[(size_t)BB * 256 * NN];
__device__ float g_qr [64 * 2048];               // (b*8+h, d*64+r)
__device__ float g_kr [64 * 2048];
__device__ float g_vr [64 * 2048];
__device__ float g_vals[64 * 2048];

// ---------------- zero the atomic-accumulated buffers (every launch!) ---------
__global__ void zero3_k(float* qr, float* kr, float* vr) {
    int i = blockIdx.x * 256 + threadIdx.x;
    if (i < 64 * 2048) { qr[i] = 0.f; kr[i] = 0.f; vr[i] = 0.f; }
}

// ---------------- generic conv1x1 GEMM: Y[b] = W(MxK) @ X[b](KxN) + bias ------
// mode 0: plain write.  mode 1: Y = tgt + alpha*(acc + bias)  (final residual)
__global__ __launch_bounds__(256) void gemm_bias_k(
    const float* __restrict__ W, const float* __restrict__ bias,
    const float* __restrict__ X, float* __restrict__ Y, int M,
    int mode, const float* __restrict__ tgt, const float* __restrict__ alphap)
{
    __shared__ float As[16 * 66];    // As[k][m], padded row 66
    __shared__ float Bs[16 * 128];   // Bs[k][n]

    const int tid = threadIdx.x;
    const int n0  = blockIdx.x * 128;
    const int m0  = blockIdx.y * 64;
    const int b   = blockIdx.z;
    const float* Xb = X + (size_t)b * KK * NN;

    const int arow = tid >> 2;       // 0..63
    const int akq  = tid & 3;        // 0..3
    const int brow = tid >> 5;       // 0..7
    const int bc4  = tid & 31;       // 0..31
    const int ty   = tid >> 4;       // 0..15
    const int tx   = tid & 15;       // 0..15

    float acc[4][8];
    #pragma unroll
    for (int i = 0; i < 4; i++)
        #pragma unroll
        for (int j = 0; j < 8; j++) acc[i][j] = 0.f;

    for (int k0 = 0; k0 < KK; k0 += 16) {
        float4 av = *(const float4*)(W + (size_t)(m0 + arow) * KK + k0 + akq * 4);
        As[(akq * 4 + 0) * 66 + arow] = av.x;
        As[(akq * 4 + 1) * 66 + arow] = av.y;
        As[(akq * 4 + 2) * 66 + arow] = av.z;
        As[(akq * 4 + 3) * 66 + arow] = av.w;
        float4 b0 = *(const float4*)(Xb + (size_t)(k0 + brow) * NN + n0 + bc4 * 4);
        float4 b1 = *(const float4*)(Xb + (size_t)(k0 + brow + 8) * NN + n0 + bc4 * 4);
        *(float4*)&Bs[(brow)     * 128 + bc4 * 4] = b0;
        *(float4*)&Bs[(brow + 8) * 128 + bc4 * 4] = b1;
        __syncthreads();
        #pragma unroll
        for (int k = 0; k < 16; k++) {
            float2 a01 = *(float2*)&As[k * 66 + ty * 2];
            float2 a23 = *(float2*)&As[k * 66 + 32 + ty * 2];
            float4 b03 = *(float4*)&Bs[k * 128 + tx * 4];
            float4 b47 = *(float4*)&Bs[k * 128 + 64 + tx * 4];
            float a[4]  = { a01.x, a01.y, a23.x, a23.y };
            float bv[8] = { b03.x, b03.y, b03.z, b03.w, b47.x, b47.y, b47.z, b47.w };
            #pragma unroll
            for (int i = 0; i < 4; i++)
                #pragma unroll
                for (int j = 0; j < 8; j++)
                    acc[i][j] += a[i] * bv[j];
        }
        __syncthreads();
    }

    float al = (mode == 1) ? *alphap : 0.f;
    #pragma unroll
    for (int i = 0; i < 4; i++) {
        int m = m0 + ((i < 2) ? (ty * 2 + i) : (32 + ty * 2 + (i - 2)));
        float bi = bias[m];
        size_t ybase = ((size_t)b * M + m) * NN + n0;
        if (mode == 0) {
            float4 o0 = { acc[i][0] + bi, acc[i][1] + bi, acc[i][2] + bi, acc[i][3] + bi };
            float4 o1 = { acc[i][4] + bi, acc[i][5] + bi, acc[i][6] + bi, acc[i][7] + bi };
            *(float4*)(Y + ybase + tx * 4)      = o0;
            *(float4*)(Y + ybase + 64 + tx * 4) = o1;
        } else {
            size_t tbase = ((size_t)b * 256 + m) * NN + n0;
            float4 t0 = *(const float4*)(tgt + tbase + tx * 4);
            float4 t1 = *(const float4*)(tgt + tbase + 64 + tx * 4);
            float4 o0 = { t0.x + al * (acc[i][0] + bi), t0.y + al * (acc[i][1] + bi),
                          t0.z + al * (acc[i][2] + bi), t0.w + al * (acc[i][3] + bi) };
            float4 o1 = { t1.x + al * (acc[i][4] + bi), t1.y + al * (acc[i][5] + bi),
                          t1.z + al * (acc[i][6] + bi), t1.w + al * (acc[i][7] + bi) };
            *(float4*)(Y + ybase + tx * 4)      = o0;
            *(float4*)(Y + ybase + 64 + tx * 4) = o1;
        }
    }
}

// ---------------- channel softmax over 512 channels, per spatial column -------
__global__ __launch_bounds__(256) void softmax512_k(float* __restrict__ P)
{
    int n = blockIdx.y * 256 + threadIdx.x;
    size_t base = (size_t)blockIdx.x * 512 * NN + n;
    float m = -1e30f, s = 0.f;
    for (int c = 0; c < 512; c++) {
        float x = P[base + (size_t)c * NN];
        float nm = fmaxf(m, x);
        s = s * __expf(m - nm) + __expf(x - nm);
        m = nm;
    }
    float inv = 1.f / s;
    for (int c = 0; c < 512; c++) {
        float x = P[base + (size_t)c * NN];
        P[base + (size_t)c * NN] = __expf(x - m) * inv;
    }
}

// ---------------- outer reduce: out[bh](32x64) += A(32,N) @ Rm(64,N)^T --------
__global__ __launch_bounds__(256) void outer_reduce_k(
    const float* __restrict__ A, int CA, int HA, int OA,
    const float* __restrict__ Rm, float* __restrict__ out)
{
    __shared__ float As2[32 * 34];   // [c][d]
    __shared__ float Rs [32 * 68];   // [c][r]
    int bh = blockIdx.x; int b = bh >> 3, h = bh & 7;
    const float* Ab = A  + ((size_t)b * CA  + h * HA + OA) * NN;
    const float* Rb = Rm + ((size_t)b * 512 + h * 64) * NN;
    float* o = out + (size_t)bh * 2048;
    int t  = threadIdx.x;
    int d0 = (t & 15) * 2;
    int r0 = (t >> 4) * 4;
    float acc[2][4] = {};
    int nbeg = blockIdx.y * 1024;
    for (int n0 = nbeg; n0 < nbeg + 1024; n0 += 32) {
        #pragma unroll
        for (int i = 0; i < 4; i++) {        // 32x32 A tile
            int e = t + i * 256;
            int d = e >> 5, c = e & 31;
            As2[c * 34 + d] = Ab[(size_t)d * NN + n0 + c];
        }
        #pragma unroll
        for (int i = 0; i < 8; i++) {        // 64x32 R tile
            int e = t + i * 256;
            int r = e >> 5, c = e & 31;
            Rs[c * 68 + r] = Rb[(size_t)r * NN + n0 + c];
        }
        __syncthreads();
        #pragma unroll
        for (int c = 0; c < 32; c++) {
            float2 a  = *(float2*)&As2[c * 34 + d0];
            float4 rv = *(float4*)&Rs [c * 68 + r0];
            acc[0][0] += a.x * rv.x; acc[0][1] += a.x * rv.y;
            acc[0][2] += a.x * rv.z; acc[0][3] += a.x * rv.w;
            acc[1][0] += a.y * rv.x; acc[1][1] += a.y * rv.y;
            acc[1][2] += a.y * rv.z; acc[1][3] += a.y * rv.w;
        }
        __syncthreads();
    }
    #pragma unroll
    for (int i = 0; i < 2; i++)
        #pragma unroll
        for (int j = 0; j < 4; j++)
            atomicAdd(&o[(d0 + i) * 64 + r0 + j], acc[i][j]);
}

// ---------------- tiny attention per (b,h): 64x64 scores over d=32 ------------
__global__ __launch_bounds__(64) void attn_k(
    const float* __restrict__ qr, const float* __restrict__ kr,
    const float* __restrict__ vr, float* __restrict__ vals)
{
    int bh = blockIdx.x; int t = threadIdx.x;   // t = query-region index
    __shared__ float sq[2048], sk[2048], sv[2048];
    const float* pq = qr + (size_t)bh * 2048;
    const float* pk = kr + (size_t)bh * 2048;
    const float* pv = vr + (size_t)bh * 2048;
    for (int i = t; i < 2048; i += 64) { sq[i] = pq[i]; sk[i] = pk[i]; sv[i] = pv[i]; }
    __syncthreads();

    float sc[64];
    #pragma unroll 4
    for (int k = 0; k < 64; k++) {
        float s = 0.f;
        #pragma unroll
        for (int d = 0; d < 32; d++) s += sq[d * 64 + t] * sk[d * 64 + k];
        sc[k] = s * 0.17677669529663687f;   // 1/sqrt(32)
    }
    float m = -1e30f;
    #pragma unroll
    for (int k = 0; k < 64; k++) m = fmaxf(m, sc[k]);
    float s = 0.f;
    #pragma unroll
    for (int k = 0; k < 64; k++) { sc[k] = __expf(sc[k] - m); s += sc[k]; }
    float inv = 1.f / s;
    #pragma unroll
    for (int k = 0; k < 64; k++) sc[k] *= inv;

    #pragma unroll 4
    for (int d = 0; d < 32; d++) {
        float v = 0.f;
        #pragma unroll
        for (int k = 0; k < 64; k++) v += sv[d * 64 + k] * sc[k];
        vals[(size_t)bh * 2048 + d * 64 + t] = v;
    }
}

// ---------------- tok[b,h,d,n] = sum_r vals[b,h,d,r] * Rq[b,h,r,n] ------------
__global__ __launch_bounds__(256) void tok_k(
    const float* __restrict__ vals, const float* __restrict__ Rq,
    float* __restrict__ tok)
{
    int bh = blockIdx.x; int b = bh >> 3, h = bh & 7;
    int n = blockIdx.y * 256 + threadIdx.x;
    __shared__ float vs[2048];
    const float* pv = vals + (size_t)bh * 2048;
    for (int i = threadIdx.x; i < 2048; i += 256) vs[i] = pv[i];
    __syncthreads();
    const float* Rb = Rq + ((size_t)b * 512 + h * 64) * NN + n;
    float acc[32] = {};
    #pragma unroll 4
    for (int r = 0; r < 64; r++) {
        float rv = Rb[(size_t)r * NN];
        #pragma unroll
        for (int d = 0; d < 32; d++) acc[d] += vs[d * 64 + r] * rv;
    }
    float* op = tok + ((size_t)b * 256 + h * 32) * NN + n;
    #pragma unroll
    for (int d = 0; d < 32; d++) op[(size_t)d * NN] = acc[d];
}

// ------------------------------ launcher --------------------------------------
extern "C" void kernel_launch(void* const* d_in, const int* in_sizes, int n_in,
                              void* d_out, int out_size)
{
    const float* src   = (const float*)d_in[0];
    const float* tgt   = (const float*)d_in[1];
    const float* Wq    = (const float*)d_in[2];
    const float* bq    = (const float*)d_in[3];
    const float* Wkv   = (const float*)d_in[4];
    const float* bkv   = (const float*)d_in[5];
    const float* Wrq   = (const float*)d_in[6];
    const float* brq   = (const float*)d_in[7];
    const float* Wrk   = (const float*)d_in[8];
    const float* brk   = (const float*)d_in[9];
    const float* Wout  = (const float*)d_in[10];
    const float* bout  = (const float*)d_in[11];
    const float* alpha = (const float*)d_in[12];
    float* out = (float*)d_out;

    float *pq, *pkv, *pRq, *pRk, *ptok, *pqr, *pkr, *pvr, *pvals;
    cudaGetSymbolAddress((void**)&pq,    g_q);
    cudaGetSymbolAddress((void**)&pkv,   g_kv);
    cudaGetSymbolAddress((void**)&pRq,   g_Rq);
    cudaGetSymbolAddress((void**)&pRk,   g_Rk);
    cudaGetSymbolAddress((void**)&ptok,  g_tok);
    cudaGetSymbolAddress((void**)&pqr,   g_qr);
    cudaGetSymbolAddress((void**)&pkr,   g_kr);
    cudaGetSymbolAddress((void**)&pvr,   g_vr);
    cudaGetSymbolAddress((void**)&pvals, g_vals);

    // zero atomic accumulators (graph replays!)
    zero3_k<<<512, 256>>>(pqr, pkr, pvr);

    const dim3 gB(NN / 128, 4, BB);   // M=256
    const dim3 gB2(NN / 128, 8, BB);  // M=512

    gemm_bias_k<<<gB,  256>>>(Wq,  bq,  tgt, pq,  256, 0, nullptr, nullptr);
    gemm_bias_k<<<gB2, 256>>>(Wkv, bkv, src, pkv, 512, 0, nullptr, nullptr);
    gemm_bias_k<<<gB2, 256>>>(Wrq, brq, tgt, pRq, 512, 0, nullptr, nullptr);
    gemm_bias_k<<<gB2, 256>>>(Wrk, brk, src, pRk, 512, 0, nullptr, nullptr);

    softmax512_k<<<dim3(BB, NN / 256), 256>>>(pRq);
    softmax512_k<<<dim3(BB, NN / 256), 256>>>(pRk);

    // qr = q x Rq^T ;  kr = k x Rk^T ; vr = v x Rk^T
    outer_reduce_k<<<dim3(64, 9), 256>>>(pq,  256, 32,  0, pRq, pqr);
    outer_reduce_k<<<dim3(64, 9), 256>>>(pkv, 512, 64,  0, pRk, pkr);
    outer_reduce_k<<<dim3(64, 9), 256>>>(pkv, 512, 64, 32, pRk, pvr);

    attn_k<<<64, 64>>>(pqr, pkr, pvr, pvals);

    tok_k<<<dim3(64, NN / 256), 256>>>(pvals, pRq, ptok);

    gemm_bias_k<<<gB, 256>>>(Wout, bout, ptok, out, 256, 1, tgt, alpha);
}

// round 2
// speedup vs baseline: 1.9903x; 1.9903x over previous
#include <cuda_runtime.h>
#include <cuda_bf16.h>
#include <math.h>
#include <stdint.h>

typedef __nv_bfloat16 bf16;

#define BB   8
#define NN   9216      // 96*96
#define KK   256

// ---------------- scratch -----------------------------------------------------
__device__ float g_q  [(size_t)BB * 256 * NN];
__device__ float g_kv [(size_t)BB * 512 * NN];
__device__ float g_Rq [(size_t)BB * 512 * NN];
__device__ float g_Rk [(size_t)BB * 512 * NN];
__device__ bf16  g_tokb[(size_t)BB * 256 * NN];
__device__ bf16  g_srcb[(size_t)BB * 256 * NN];
__device__ bf16  g_tgtb[(size_t)BB * 256 * NN];
__device__ bf16  g_Wqb [256 * 256];
__device__ bf16  g_Wkvb[512 * 256];
__device__ bf16  g_Wrqb[512 * 256];
__device__ bf16  g_Wrkb[512 * 256];
__device__ bf16  g_Woutb[256 * 256];
__device__ float g_qr  [64 * 2048];
__device__ float g_kr  [64 * 2048];
__device__ float g_vr  [64 * 2048];
__device__ float g_vals[64 * 2048];

// ---------------- fp32 -> bf16 conversion -------------------------------------
__global__ __launch_bounds__(256) void cvt_k(const float* __restrict__ x,
                                             bf16* __restrict__ y, int n4)
{
    int i = blockIdx.x * 256 + threadIdx.x;
    if (i < n4) {
        float4 v = *(const float4*)(x + (size_t)i * 4);
        __nv_bfloat162 h0 = { __float2bfloat16(v.x), __float2bfloat16(v.y) };
        __nv_bfloat162 h1 = { __float2bfloat16(v.z), __float2bfloat16(v.w) };
        *(__nv_bfloat162*)(y + (size_t)i * 4)     = h0;
        *(__nv_bfloat162*)(y + (size_t)i * 4 + 2) = h1;
    }
}

__global__ void zero3_k(float* qr, float* kr, float* vr) {
    int i = blockIdx.x * 256 + threadIdx.x;
    if (i < 64 * 2048) { qr[i] = 0.f; kr[i] = 0.f; vr[i] = 0.f; }
}

// ---------------- PTX helpers -------------------------------------------------
__device__ __forceinline__ uint32_t s2u(const void* p) {
    return (uint32_t)__cvta_generic_to_shared(p);
}
__device__ __forceinline__ void ldsm4(uint32_t& r0, uint32_t& r1, uint32_t& r2,
                                      uint32_t& r3, uint32_t a) {
    asm volatile("ldmatrix.sync.aligned.m8n8.x4.shared.b16 {%0,%1,%2,%3},[%4];\n"
        : "=r"(r0), "=r"(r1), "=r"(r2), "=r"(r3) : "r"(a));
}
__device__ __forceinline__ void ldsm4t(uint32_t& r0, uint32_t& r1, uint32_t& r2,
                                       uint32_t& r3, uint32_t a) {
    asm volatile("ldmatrix.sync.aligned.m8n8.x4.trans.shared.b16 {%0,%1,%2,%3},[%4];\n"
        : "=r"(r0), "=r"(r1), "=r"(r2), "=r"(r3) : "r"(a));
}
__device__ __forceinline__ void mma16816(float* c, const uint32_t* a,
                                         uint32_t b0, uint32_t b1) {
    asm volatile(
        "mma.sync.aligned.m16n8k16.row.col.f32.bf16.bf16.f32 "
        "{%0,%1,%2,%3},{%4,%5,%6,%7},{%8,%9},{%0,%1,%2,%3};\n"
        : "+f"(c[0]), "+f"(c[1]), "+f"(c[2]), "+f"(c[3])
        : "r"(a[0]), "r"(a[1]), "r"(a[2]), "r"(a[3]), "r"(b0), "r"(b1));
}
__device__ __forceinline__ void cpasync16(uint32_t s, const void* g) {
    asm volatile("cp.async.cg.shared.global [%0], [%1], 16;\n" :: "r"(s), "l"(g));
}
__device__ __forceinline__ void cp_commit() { asm volatile("cp.async.commit_group;\n"); }
__device__ __forceinline__ void cp_wait0()  { asm volatile("cp.async.wait_group 0;\n"); }

// ---------------- bf16 tensor-core GEMM: Y[b] = W(MxK) @ X[b](KxN) + bias -----
// CTA tile 128x128, BK=32, 8 warps (warp tile 32x64), double-buffered cp.async.
// mode 0: plain fp32 write.  mode 1: Y = tgt + alpha*(acc + bias).
#define APAD 40    // A smem row stride (elems): conflict-free ldmatrix
#define BPAD 136   // B smem row stride

__global__ __launch_bounds__(256) void hgemm_k(
    const bf16* __restrict__ Wb, const float* __restrict__ bias,
    const bf16* __restrict__ Xb, float* __restrict__ Y, int M,
    int mode, const float* __restrict__ tgt, const float* __restrict__ alphap)
{
    __shared__ bf16 sA[2][128 * APAD];
    __shared__ bf16 sB[2][32 * BPAD];

    const int tid  = threadIdx.x;
    const int warp = tid >> 5, lane = tid & 31;
    const int wm   = warp >> 1, wn = warp & 1;
    const int n0   = blockIdx.x * 128;
    const int m0   = blockIdx.y * 128;
    const int b    = blockIdx.z;
    const bf16* X  = Xb + (size_t)b * KK * NN;

    float acc[2][8][4];
    #pragma unroll
    for (int i = 0; i < 2; i++)
        #pragma unroll
        for (int j = 0; j < 8; j++)
            #pragma unroll
            for (int k = 0; k < 4; k++) acc[i][j][k] = 0.f;

    // gmem->smem load geometry (per thread: 2 A-chunks + 2 B-chunks of 16B)
    const int ac0 = tid, ac1 = tid + 256;             // A chunk ids (512 total)
    const int bc0 = tid, bc1 = tid + 256;             // B chunk ids (512 total)

    auto issue_tile = [&](int kt, int buf) {
        // A: rows m0..m0+127, cols kt*32..+32
        {
            int r0 = ac0 >> 2, k0 = (ac0 & 3) * 8;
            int r1 = ac1 >> 2, k1 = (ac1 & 3) * 8;
            cpasync16(s2u(&sA[buf][r0 * APAD + k0]), Wb + (size_t)(m0 + r0) * KK + kt * 32 + k0);
            cpasync16(s2u(&sA[buf][r1 * APAD + k1]), Wb + (size_t)(m0 + r1) * KK + kt * 32 + k1);
        }
        // B: rows kt*32..+32, cols n0..n0+127
        {
            int r0 = bc0 >> 4, c0 = (bc0 & 15) * 8;
            int r1 = bc1 >> 4, c1 = (bc1 & 15) * 8;
            cpasync16(s2u(&sB[buf][r0 * BPAD + c0]), X + (size_t)(kt * 32 + r0) * NN + n0 + c0);
            cpasync16(s2u(&sB[buf][r1 * BPAD + c1]), X + (size_t)(kt * 32 + r1) * NN + n0 + c1);
        }
        cp_commit();
    };

    issue_tile(0, 0);
    cp_wait0();
    __syncthreads();

    for (int kt = 0; kt < 8; kt++) {
        int cur = kt & 1;
        if (kt < 7) issue_tile(kt + 1, cur ^ 1);

        #pragma unroll
        for (int ks = 0; ks < 2; ks++) {
            uint32_t a[2][4];
            #pragma unroll
            for (int mt = 0; mt < 2; mt++) {
                int row = wm * 32 + mt * 16 + (lane & 15);
                int col = ks * 16 + (lane >> 4) * 8;
                ldsm4(a[mt][0], a[mt][1], a[mt][2], a[mt][3],
                      s2u(&sA[cur][row * APAD + col]));
            }
            uint32_t bf[4][4];
            #pragma unroll
            for (int ntg = 0; ntg < 4; ntg++) {
                int row = ks * 16 + (lane & 15);
                int col = wn * 64 + ntg * 16 + (lane >> 4) * 8;
                ldsm4t(bf[ntg][0], bf[ntg][1], bf[ntg][2], bf[ntg][3],
                       s2u(&sB[cur][row * BPAD + col]));
            }
            #pragma unroll
            for (int mt = 0; mt < 2; mt++)
                #pragma unroll
                for (int nt = 0; nt < 8; nt++) {
                    int ntg = nt >> 1, half = nt & 1;
                    mma16816(acc[mt][nt], a[mt], bf[ntg][half * 2], bf[ntg][half * 2 + 1]);
                }
        }

        if (kt < 7) { cp_wait0(); __syncthreads(); }
    }

    // epilogue
    float al = (mode == 1) ? *alphap : 0.f;
    #pragma unroll
    for (int mt = 0; mt < 2; mt++) {
        #pragma unroll
        for (int rr = 0; rr < 2; rr++) {
            int m = m0 + wm * 32 + mt * 16 + rr * 8 + (lane >> 2);
            float bi = bias[m];
            size_t ybase = ((size_t)b * M + m) * NN + n0;
            #pragma unroll
            for (int nt = 0; nt < 8; nt++) {
                int n = wn * 64 + nt * 8 + (lane & 3) * 2;
                float c0 = acc[mt][nt][rr * 2 + 0] + bi;
                float c1 = acc[mt][nt][rr * 2 + 1] + bi;
                if (mode == 0) {
                    float2 o = { c0, c1 };
                    *(float2*)(Y + ybase + n) = o;
                } else {
                    size_t tbase = ((size_t)b * 256 + m) * NN + n0;
                    float2 t = *(const float2*)(tgt + tbase + n);
                    float2 o = { t.x + al * c0, t.y + al * c1 };
                    *(float2*)(Y + ybase + n) = o;
                }
            }
        }
    }
}

// ---------------- channel softmax over 512 channels, per spatial column -------
__global__ __launch_bounds__(256) void softmax512_k(float* __restrict__ P)
{
    int n = blockIdx.y * 256 + threadIdx.x;
    size_t base = (size_t)blockIdx.x * 512 * NN + n;
    float m = -1e30f, s = 0.f;
    for (int c = 0; c < 512; c++) {
        float x = P[base + (size_t)c * NN];
        float nm = fmaxf(m, x);
        s = s * __expf(m - nm) + __expf(x - nm);
        m = nm;
    }
    float inv = 1.f / s;
    for (int c = 0; c < 512; c++) {
        float x = P[base + (size_t)c * NN];
        P[base + (size_t)c * NN] = __expf(x - m) * inv;
    }
}

// ---------------- outer reduce: out[bh](32x64) += A(32,N) @ Rm(64,N)^T --------
__global__ __launch_bounds__(256) void outer_reduce_k(
    const float* __restrict__ A, int CA, int HA, int OA,
    const float* __restrict__ Rm, float* __restrict__ out)
{
    __shared__ float As2[32 * 34];
    __shared__ float Rs [32 * 68];
    int bh = blockIdx.x; int b = bh >> 3, h = bh & 7;
    const float* Ab = A  + ((size_t)b * CA  + h * HA + OA) * NN;
    const float* Rb = Rm + ((size_t)b * 512 + h * 64) * NN;
    float* o = out + (size_t)bh * 2048;
    int t  = threadIdx.x;
    int d0 = (t & 15) * 2;
    int r0 = (t >> 4) * 4;
    float acc[2][4] = {};
    int nbeg = blockIdx.y * 1024;
    for (int n0 = nbeg; n0 < nbeg + 1024; n0 += 32) {
        #pragma unroll
        for (int i = 0; i < 4; i++) {
            int e = t + i * 256;
            int d = e >> 5, c = e & 31;
            As2[c * 34 + d] = Ab[(size_t)d * NN + n0 + c];
        }
        #pragma unroll
        for (int i = 0; i < 8; i++) {
            int e = t + i * 256;
            int r = e >> 5, c = e & 31;
            Rs[c * 68 + r] = Rb[(size_t)r * NN + n0 + c];
        }
        __syncthreads();
        #pragma unroll
        for (int c = 0; c < 32; c++) {
            float2 a  = *(float2*)&As2[c * 34 + d0];
            float4 rv = *(float4*)&Rs [c * 68 + r0];
            acc[0][0] += a.x * rv.x; acc[0][1] += a.x * rv.y;
            acc[0][2] += a.x * rv.z; acc[0][3] += a.x * rv.w;
            acc[1][0] += a.y * rv.x; acc[1][1] += a.y * rv.y;
            acc[1][2] += a.y * rv.z; acc[1][3] += a.y * rv.w;
        }
        __syncthreads();
    }
    #pragma unroll
    for (int i = 0; i < 2; i++)
        #pragma unroll
        for (int j = 0; j < 4; j++)
            atomicAdd(&o[(d0 + i) * 64 + r0 + j], acc[i][j]);
}

// ---------------- tiny attention per (b,h) ------------------------------------
__global__ __launch_bounds__(64) void attn_k(
    const float* __restrict__ qr, const float* __restrict__ kr,
    const float* __restrict__ vr, float* __restrict__ vals)
{
    int bh = blockIdx.x; int t = threadIdx.x;
    __shared__ float sq[2048], sk[2048], sv[2048];
    const float* pq = qr + (size_t)bh * 2048;
    const float* pk = kr + (size_t)bh * 2048;
    const float* pv = vr + (size_t)bh * 2048;
    for (int i = t; i < 2048; i += 64) { sq[i] = pq[i]; sk[i] = pk[i]; sv[i] = pv[i]; }
    __syncthreads();

    float sc[64];
    #pragma unroll 4
    for (int k = 0; k < 64; k++) {
        float s = 0.f;
        #pragma unroll
        for (int d = 0; d < 32; d++) s += sq[d * 64 + t] * sk[d * 64 + k];
        sc[k] = s * 0.17677669529663687f;
    }
    float m = -1e30f;
    #pragma unroll
    for (int k = 0; k < 64; k++) m = fmaxf(m, sc[k]);
    float s = 0.f;
    #pragma unroll
    for (int k = 0; k < 64; k++) { sc[k] = __expf(sc[k] - m); s += sc[k]; }
    float inv = 1.f / s;
    #pragma unroll
    for (int k = 0; k < 64; k++) sc[k] *= inv;

    #pragma unroll 4
    for (int d = 0; d < 32; d++) {
        float v = 0.f;
        #pragma unroll
        for (int k = 0; k < 64; k++) v += sv[d * 64 + k] * sc[k];
        vals[(size_t)bh * 2048 + d * 64 + t] = v;
    }
}

// ---------------- tok (bf16 out): tok[b,h,d,n] = sum_r vals*Rq ----------------
__global__ __launch_bounds__(256) void tok_k(
    const float* __restrict__ vals, const float* __restrict__ Rq,
    bf16* __restrict__ tok)
{
    int bh = blockIdx.x; int b = bh >> 3, h = bh & 7;
    int n = blockIdx.y * 256 + threadIdx.x;
    __shared__ float vs[2048];
    const float* pv = vals + (size_t)bh * 2048;
    for (int i = threadIdx.x; i < 2048; i += 256) vs[i] = pv[i];
    __syncthreads();
    const float* Rb = Rq + ((size_t)b * 512 + h * 64) * NN + n;
    float acc[32] = {};
    #pragma unroll 4
    for (int r = 0; r < 64; r++) {
        float rv = Rb[(size_t)r * NN];
        #pragma unroll
        for (int d = 0; d < 32; d++) acc[d] += vs[d * 64 + r] * rv;
    }
    bf16* op = tok + ((size_t)b * 256 + h * 32) * NN + n;
    #pragma unroll
    for (int d = 0; d < 32; d++) op[(size_t)d * NN] = __float2bfloat16(acc[d]);
}

// ------------------------------ launcher --------------------------------------
extern "C" void kernel_launch(void* const* d_in, const int* in_sizes, int n_in,
                              void* d_out, int out_size)
{
    const float* src   = (const float*)d_in[0];
    const float* tgt   = (const float*)d_in[1];
    const float* Wq    = (const float*)d_in[2];
    const float* bq    = (const float*)d_in[3];
    const float* Wkv   = (const float*)d_in[4];
    const float* bkv   = (const float*)d_in[5];
    const float* Wrq   = (const float*)d_in[6];
    const float* brq   = (const float*)d_in[7];
    const float* Wrk   = (const float*)d_in[8];
    const float* brk   = (const float*)d_in[9];
    const float* Wout  = (const float*)d_in[10];
    const float* bout  = (const float*)d_in[11];
    const float* alpha = (const float*)d_in[12];
    float* out = (float*)d_out;

    float *pq, *pkv, *pRq, *pRk, *pqr, *pkr, *pvr, *pvals;
    bf16 *ptokb, *psrcb, *ptgtb, *pWq, *pWkv, *pWrq, *pWrk, *pWout;
    cudaGetSymbolAddress((void**)&pq,    g_q);
    cudaGetSymbolAddress((void**)&pkv,   g_kv);
    cudaGetSymbolAddress((void**)&pRq,   g_Rq);
    cudaGetSymbolAddress((void**)&pRk,   g_Rk);
    cudaGetSymbolAddress((void**)&ptokb, g_tokb);
    cudaGetSymbolAddress((void**)&psrcb, g_srcb);
    cudaGetSymbolAddress((void**)&ptgtb, g_tgtb);
    cudaGetSymbolAddress((void**)&pWq,   g_Wqb);
    cudaGetSymbolAddress((void**)&pWkv,  g_Wkvb);
    cudaGetSymbolAddress((void**)&pWrq,  g_Wrqb);
    cudaGetSymbolAddress((void**)&pWrk,  g_Wrkb);
    cudaGetSymbolAddress((void**)&pWout, g_Woutb);
    cudaGetSymbolAddress((void**)&pqr,   g_qr);
    cudaGetSymbolAddress((void**)&pkr,   g_kr);
    cudaGetSymbolAddress((void**)&pvr,   g_vr);
    cudaGetSymbolAddress((void**)&pvals, g_vals);

    zero3_k<<<512, 256>>>(pqr, pkr, pvr);

    // conversions to bf16
    const int actN4 = (BB * 256 * NN) / 4;
    cvt_k<<<(actN4 + 255) / 256, 256>>>(src, psrcb, actN4);
    cvt_k<<<(actN4 + 255) / 256, 256>>>(tgt, ptgtb, actN4);
    cvt_k<<<(256 * 256 / 4 + 255) / 256, 256>>>(Wq,   pWq,   256 * 256 / 4);
    cvt_k<<<(512 * 256 / 4 + 255) / 256, 256>>>(Wkv,  pWkv,  512 * 256 / 4);
    cvt_k<<<(512 * 256 / 4 + 255) / 256, 256>>>(Wrq,  pWrq,  512 * 256 / 4);
    cvt_k<<<(512 * 256 / 4 + 255) / 256, 256>>>(Wrk,  pWrk,  512 * 256 / 4);
    cvt_k<<<(256 * 256 / 4 + 255) / 256, 256>>>(Wout, pWout, 256 * 256 / 4);

    const dim3 gB (NN / 128, 2, BB);   // M=256
    const dim3 gB2(NN / 128, 4, BB);   // M=512

    hgemm_k<<<gB,  256>>>(pWq,  bq,  ptgtb, pq,  256, 0, nullptr, nullptr);
    hgemm_k<<<gB2, 256>>>(pWkv, bkv, psrcb, pkv, 512, 0, nullptr, nullptr);
    hgemm_k<<<gB2, 256>>>(pWrq, brq, ptgtb, pRq, 512, 0, nullptr, nullptr);
    hgemm_k<<<gB2, 256>>>(pWrk, brk, psrcb, pRk, 512, 0, nullptr, nullptr);

    softmax512_k<<<dim3(BB, NN / 256), 256>>>(pRq);
    softmax512_k<<<dim3(BB, NN / 256), 256>>>(pRk);

    outer_reduce_k<<<dim3(64, 9), 256>>>(pq,  256, 32,  0, pRq, pqr);
    outer_reduce_k<<<dim3(64, 9), 256>>>(pkv, 512, 64,  0, pRk, pkr);
    outer_reduce_k<<<dim3(64, 9), 256>>>(pkv, 512, 64, 32, pRk, pvr);

    attn_k<<<64, 64>>>(pqr, pkr, pvr, pvals);

    tok_k<<<dim3(64, NN / 256), 256>>>(pvals, pRq, ptokb);

    hgemm_k<<<gB, 256>>>(pWout, bout, ptokb, out, 256, 1, tgt, alpha);
}

// round 4
// speedup vs baseline: 2.6357x; 1.3243x over previous
#include <cuda_runtime.h>
#include <cuda_bf16.h>
#include <math.h>
#include <stdint.h>

typedef __nv_bfloat16 bf16;

#define BB   8
#define NN   9216
#define KK   256

// ---------------- scratch -----------------------------------------------------
__device__ bf16  g_q  [(size_t)BB * 256 * NN];
__device__ bf16  g_kv [(size_t)BB * 512 * NN];
__device__ bf16  g_Rq [(size_t)BB * 512 * NN];
__device__ bf16  g_Rk [(size_t)BB * 512 * NN];
__device__ bf16  g_tokb[(size_t)BB * 256 * NN];
__device__ bf16  g_srcb[(size_t)BB * 256 * NN];
__device__ bf16  g_tgtb[(size_t)BB * 256 * NN];
__device__ bf16  g_Wqb [256 * 256];
__device__ bf16  g_Wkvb[512 * 256];
__device__ bf16  g_Wrqb[512 * 256];
__device__ bf16  g_Wrkb[512 * 256];
__device__ bf16  g_Woutb[256 * 256];
__device__ float g_qr  [64 * 32 * 64];    // (bh, d, r)
__device__ float g_krvr[64 * 64 * 64];    // (bh, d∈[0,32)=k | [32,64)=v, r)
__device__ float g_vals[64 * 2048];

// ---------------- conversions -------------------------------------------------
__global__ __launch_bounds__(256) void cvt_k(const float* __restrict__ x,
                                             bf16* __restrict__ y, int n4)
{
    int i = blockIdx.x * 256 + threadIdx.x;
    if (i < n4) {
        float4 v = *(const float4*)(x + (size_t)i * 4);
        __nv_bfloat162 h0 = { __float2bfloat16(v.x), __float2bfloat16(v.y) };
        __nv_bfloat162 h1 = { __float2bfloat16(v.z), __float2bfloat16(v.w) };
        *(__nv_bfloat162*)(y + (size_t)i * 4)     = h0;
        *(__nv_bfloat162*)(y + (size_t)i * 4 + 2) = h1;
    }
}

// all 5 weight matrices in one launch (keeps launch #5 = big hgemm for ncu)
__global__ __launch_bounds__(256) void cvt5_k(
    const float* s0, const float* s1, const float* s2, const float* s3, const float* s4,
    bf16* d0, bf16* d1, bf16* d2, bf16* d3, bf16* d4)
{
    int i = blockIdx.x * 256 + threadIdx.x;   // chunk of 4
    const float* s; bf16* d; int o;
    if      (i <  16384) { s = s0; d = d0; o = i; }
    else if (i <  49152) { s = s1; d = d1; o = i - 16384; }
    else if (i <  81920) { s = s2; d = d2; o = i - 49152; }
    else if (i < 114688) { s = s3; d = d3; o = i - 81920; }
    else if (i < 131072) { s = s4; d = d4; o = i - 114688; }
    else return;
    float4 v = *(const float4*)(s + (size_t)o * 4);
    __nv_bfloat162 h0 = { __float2bfloat16(v.x), __float2bfloat16(v.y) };
    __nv_bfloat162 h1 = { __float2bfloat16(v.z), __float2bfloat16(v.w) };
    *(__nv_bfloat162*)(d + (size_t)o * 4)     = h0;
    *(__nv_bfloat162*)(d + (size_t)o * 4 + 2) = h1;
}

__global__ void zero_k(float* qr, float* krvr) {
    int i = blockIdx.x * 256 + threadIdx.x;
    if (i < 64 * 2048) qr[i] = 0.f;
    if (i < 64 * 4096) krvr[i] = 0.f;
}

// ---------------- PTX helpers -------------------------------------------------
__device__ __forceinline__ uint32_t s2u(const void* p) {
    return (uint32_t)__cvta_generic_to_shared(p);
}
__device__ __forceinline__ void ldsm4(uint32_t& r0, uint32_t& r1, uint32_t& r2,
                                      uint32_t& r3, uint32_t a) {
    asm volatile("ldmatrix.sync.aligned.m8n8.x4.shared.b16 {%0,%1,%2,%3},[%4];\n"
        : "=r"(r0), "=r"(r1), "=r"(r2), "=r"(r3) : "r"(a));
}
__device__ __forceinline__ void ldsm4t(uint32_t& r0, uint32_t& r1, uint32_t& r2,
                                       uint32_t& r3, uint32_t a) {
    asm volatile("ldmatrix.sync.aligned.m8n8.x4.trans.shared.b16 {%0,%1,%2,%3},[%4];\n"
        : "=r"(r0), "=r"(r1), "=r"(r2), "=r"(r3) : "r"(a));
}
__device__ __forceinline__ void ldsm2(uint32_t& r0, uint32_t& r1, uint32_t a) {
    asm volatile("ldmatrix.sync.aligned.m8n8.x2.shared.b16 {%0,%1},[%2];\n"
        : "=r"(r0), "=r"(r1) : "r"(a));
}
__device__ __forceinline__ void mma16816(float* c, const uint32_t* a,
                                         uint32_t b0, uint32_t b1) {
    asm volatile(
        "mma.sync.aligned.m16n8k16.row.col.f32.bf16.bf16.f32 "
        "{%0,%1,%2,%3},{%4,%5,%6,%7},{%8,%9},{%0,%1,%2,%3};\n"
        : "+f"(c[0]), "+f"(c[1]), "+f"(c[2]), "+f"(c[3])
        : "r"(a[0]), "r"(a[1]), "r"(a[2]), "r"(a[3]), "r"(b0), "r"(b1));
}
__device__ __forceinline__ void cpasync16(uint32_t s, const void* g) {
    asm volatile("cp.async.cg.shared.global [%0], [%1], 16;\n" :: "r"(s), "l"(g));
}
__device__ __forceinline__ void cp_commit() { asm volatile("cp.async.commit_group;\n"); }
__device__ __forceinline__ void cp_wait0()  { asm volatile("cp.async.wait_group 0;\n"); }

// ---------------- bf16 tensor-core GEMM ---------------------------------------
// mode 0: write bf16 to Yb.  mode 1: Yf = tgt + alpha*(acc + bias)  (fp32)
#define APAD 40
#define BPAD 136

__global__ __launch_bounds__(256) void hgemm_k(
    const bf16* __restrict__ Wb, const float* __restrict__ bias,
    const bf16* __restrict__ Xb, bf16* __restrict__ Yb, float* __restrict__ Yf,
    int M, int mode, const float* __restrict__ tgt, const float* __restrict__ alphap)
{
    __shared__ bf16 sA[2][128 * APAD];
    __shared__ bf16 sB[2][32 * BPAD];

    const int tid  = threadIdx.x;
    const int warp = tid >> 5, lane = tid & 31;
    const int wm   = warp >> 1, wn = warp & 1;
    const int n0   = blockIdx.x * 128;
    const int m0   = blockIdx.y * 128;
    const int b    = blockIdx.z;
    const bf16* X  = Xb + (size_t)b * KK * NN;

    float acc[2][8][4];
    #pragma unroll
    for (int i = 0; i < 2; i++)
        #pragma unroll
        for (int j = 0; j < 8; j++)
            #pragma unroll
            for (int k = 0; k < 4; k++) acc[i][j][k] = 0.f;

    auto issue_tile = [&](int kt, int buf) {
        {
            int r0 = tid >> 2, k0 = (tid & 3) * 8;
            cpasync16(s2u(&sA[buf][r0 * APAD + k0]),        Wb + (size_t)(m0 + r0) * KK + kt * 32 + k0);
            cpasync16(s2u(&sA[buf][(r0 + 64) * APAD + k0]), Wb + (size_t)(m0 + r0 + 64) * KK + kt * 32 + k0);
        }
        {
            int r0 = tid >> 4, c0 = (tid & 15) * 8;
            cpasync16(s2u(&sB[buf][r0 * BPAD + c0]),        X + (size_t)(kt * 32 + r0) * NN + n0 + c0);
            cpasync16(s2u(&sB[buf][(r0 + 16) * BPAD + c0]), X + (size_t)(kt * 32 + r0 + 16) * NN + n0 + c0);
        }
        cp_commit();
    };

    issue_tile(0, 0);
    cp_wait0();
    __syncthreads();

    for (int kt = 0; kt < 8; kt++) {
        int cur = kt & 1;
        if (kt < 7) issue_tile(kt + 1, cur ^ 1);

        #pragma unroll
        for (int ks = 0; ks < 2; ks++) {
            uint32_t a[2][4];
            #pragma unroll
            for (int mt = 0; mt < 2; mt++) {
                int row = wm * 32 + mt * 16 + (lane & 15);
                int col = ks * 16 + (lane >> 4) * 8;
                ldsm4(a[mt][0], a[mt][1], a[mt][2], a[mt][3],
                      s2u(&sA[cur][row * APAD + col]));
            }
            uint32_t bf[4][4];
            #pragma unroll
            for (int ntg = 0; ntg < 4; ntg++) {
                int row = ks * 16 + (lane & 15);
                int col = wn * 64 + ntg * 16 + (lane >> 4) * 8;
                ldsm4t(bf[ntg][0], bf[ntg][1], bf[ntg][2], bf[ntg][3],
                       s2u(&sB[cur][row * BPAD + col]));
            }
            #pragma unroll
            for (int mt = 0; mt < 2; mt++)
                #pragma unroll
                for (int nt = 0; nt < 8; nt++) {
                    int ntg = nt >> 1, half = nt & 1;
                    mma16816(acc[mt][nt], a[mt], bf[ntg][half * 2], bf[ntg][half * 2 + 1]);
                }
        }

        if (kt < 7) { cp_wait0(); __syncthreads(); }
    }

    float al = (mode == 1) ? *alphap : 0.f;
    #pragma unroll
    for (int mt = 0; mt < 2; mt++) {
        #pragma unroll
        for (int rr = 0; rr < 2; rr++) {
            int m = m0 + wm * 32 + mt * 16 + rr * 8 + (lane >> 2);
            float bi = bias[m];
            size_t ybase = ((size_t)b * M + m) * NN + n0;
            #pragma unroll
            for (int nt = 0; nt < 8; nt++) {
                int n = wn * 64 + nt * 8 + (lane & 3) * 2;
                float c0 = acc[mt][nt][rr * 2 + 0] + bi;
                float c1 = acc[mt][nt][rr * 2 + 1] + bi;
                if (mode == 0) {
                    __nv_bfloat162 o = { __float2bfloat16(c0), __float2bfloat16(c1) };
                    *(__nv_bfloat162*)(Yb + ybase + n) = o;
                } else {
                    size_t tbase = ((size_t)b * 256 + m) * NN + n0;
                    float2 t = *(const float2*)(tgt + tbase + n);
                    float2 o = { t.x + al * c0, t.y + al * c1 };
                    *(float2*)(Yf + ybase + n) = o;
                }
            }
        }
    }
}

// ---------------- channel softmax over 512 channels (bf16 in/out) -------------
__global__ __launch_bounds__(256) void softmax512_k(bf16* __restrict__ P)
{
    int n = blockIdx.y * 256 + threadIdx.x;
    size_t base = (size_t)blockIdx.x * 512 * NN + n;
    float m = -1e30f, s = 0.f;
    for (int c = 0; c < 512; c++) {
        float x = __bfloat162float(P[base + (size_t)c * NN]);
        float nm = fmaxf(m, x);
        s = s * __expf(m - nm) + __expf(x - nm);
        m = nm;
    }
    float inv = 1.f / s;
    for (int c = 0; c < 512; c++) {
        float x = __bfloat162float(P[base + (size_t)c * NN]);
        P[base + (size_t)c * NN] = __float2bfloat16(__expf(x - m) * inv);
    }
}

// ---------------- tensor-core outer reduce: out(AROWSx64) += A @ R^T ----------
// A rows: (b*aC + h*aH .. +AROWS), R rows: (b*512 + h*64 .. +64), K split by grid.y
template<int MR>   // AROWS = MR*16
__global__ __launch_bounds__(256) void outer_mma_k(
    const bf16* __restrict__ A, int aC, int aH,
    const bf16* __restrict__ Rm, float* __restrict__ out)
{
    constexpr int AROWS = MR * 16;
    __shared__ bf16 sA[AROWS * 72];
    __shared__ bf16 sR[64 * 72];
    int bh = blockIdx.x, b = bh >> 3, h = bh & 7;
    const bf16* Ab = A  + ((size_t)b * aC  + h * aH) * NN;
    const bf16* Rb = Rm + ((size_t)b * 512 + h * 64) * NN;
    float* ob = out + (size_t)bh * (AROWS * 64);
    int tid = threadIdx.x, warp = tid >> 5, lane = tid & 31;

    float acc[MR][4];
    #pragma unroll
    for (int i = 0; i < MR; i++)
        #pragma unroll
        for (int j = 0; j < 4; j++) acc[i][j] = 0.f;

    int kbase = blockIdx.y * 1024;
    for (int kb = 0; kb < 16; kb++) {
        int k0 = kbase + kb * 64;
        #pragma unroll
        for (int c = tid; c < AROWS * 8; c += 256) {
            int r = c >> 3, cc = (c & 7) * 8;
            cpasync16(s2u(&sA[r * 72 + cc]), Ab + (size_t)r * NN + k0 + cc);
        }
        #pragma unroll
        for (int c = tid; c < 512; c += 256) {
            int r = c >> 3, cc = (c & 7) * 8;
            cpasync16(s2u(&sR[r * 72 + cc]), Rb + (size_t)r * NN + k0 + cc);
        }
        cp_commit(); cp_wait0();
        __syncthreads();

        int r0 = warp * 8;
        #pragma unroll
        for (int ks = 0; ks < 4; ks++) {
            uint32_t a[MR][4];
            #pragma unroll
            for (int mt = 0; mt < MR; mt++)
                ldsm4(a[mt][0], a[mt][1], a[mt][2], a[mt][3],
                      s2u(&sA[(mt * 16 + (lane & 15)) * 72 + ks * 16 + (lane >> 4) * 8]));
            uint32_t b0, b1;
            {
                int j = lane & 7, half = (lane >> 3) & 1;
                ldsm2(b0, b1, s2u(&sR[(r0 + j) * 72 + ks * 16 + half * 8]));
            }
            #pragma unroll
            for (int mt = 0; mt < MR; mt++)
                mma16816(acc[mt], a[mt], b0, b1);
        }
        __syncthreads();
    }

    int row = lane >> 2, col = warp * 8 + (lane & 3) * 2;
    #pragma unroll
    for (int mt = 0; mt < MR; mt++) {
        atomicAdd(&ob[(mt * 16 + row)     * 64 + col],     acc[mt][0]);
        atomicAdd(&ob[(mt * 16 + row)     * 64 + col + 1], acc[mt][1]);
        atomicAdd(&ob[(mt * 16 + row + 8) * 64 + col],     acc[mt][2]);
        atomicAdd(&ob[(mt * 16 + row + 8) * 64 + col + 1], acc[mt][3]);
    }
}

// ---------------- tiny attention per (b,h) ------------------------------------
__global__ __launch_bounds__(64) void attn_k(
    const float* __restrict__ qr, const float* __restrict__ krvr,
    float* __restrict__ vals)
{
    int bh = blockIdx.x; int t = threadIdx.x;
    __shared__ float sq[2048], sk[2048], sv[2048];
    const float* pq = qr   + (size_t)bh * 2048;
    const float* pk = krvr + (size_t)bh * 4096;
    const float* pv = pk + 2048;
    for (int i = t; i < 2048; i += 64) { sq[i] = pq[i]; sk[i] = pk[i]; sv[i] = pv[i]; }
    __syncthreads();

    float sc[64];
    #pragma unroll 4
    for (int k = 0; k < 64; k++) {
        float s = 0.f;
        #pragma unroll
        for (int d = 0; d < 32; d++) s += sq[d * 64 + t] * sk[d * 64 + k];
        sc[k] = s * 0.17677669529663687f;
    }
    float m = -1e30f;
    #pragma unroll
    for (int k = 0; k < 64; k++) m = fmaxf(m, sc[k]);
    float s = 0.f;
    #pragma unroll
    for (int k = 0; k < 64; k++) { sc[k] = __expf(sc[k] - m); s += sc[k]; }
    float inv = 1.f / s;
    #pragma unroll
    for (int k = 0; k < 64; k++) sc[k] *= inv;

    #pragma unroll 4
    for (int d = 0; d < 32; d++) {
        float v = 0.f;
        #pragma unroll
        for (int k = 0; k < 64; k++) v += sv[d * 64 + k] * sc[k];
        vals[(size_t)bh * 2048 + d * 64 + t] = v;
    }
}

// ---------------- tok (bf16): tok[b,h,d,n] = sum_r vals * Rq ------------------
__global__ __launch_bounds__(256) void tok_k(
    const float* __restrict__ vals, const bf16* __restrict__ Rq,
    bf16* __restrict__ tok)
{
    int bh = blockIdx.x; int b = bh >> 3, h = bh & 7;
    int n = blockIdx.y * 256 + threadIdx.x;
    __shared__ float vs[2048];
    const float* pv = vals + (size_t)bh * 2048;
    for (int i = threadIdx.x; i < 2048; i += 256) vs[i] = pv[i];
    __syncthreads();
    const bf16* Rb = Rq + ((size_t)b * 512 + h * 64) * NN + n;
    float acc[32] = {};
    #pragma unroll 4
    for (int r = 0; r < 64; r++) {
        float rv = __bfloat162float(Rb[(size_t)r * NN]);
        #pragma unroll
        for (int d = 0; d < 32; d++) acc[d] += vs[d * 64 + r] * rv;
    }
    bf16* op = tok + ((size_t)b * 256 + h * 32) * NN + n;
    #pragma unroll
    for (int d = 0; d < 32; d++) op[(size_t)d * NN] = __float2bfloat16(acc[d]);
}

// ------------------------------ launcher --------------------------------------
extern "C" void kernel_launch(void* const* d_in, const int* in_sizes, int n_in,
                              void* d_out, int out_size)
{
    const float* src   = (const float*)d_in[0];
    const float* tgt   = (const float*)d_in[1];
    const float* Wq    = (const float*)d_in[2];
    const float* bq    = (const float*)d_in[3];
    const float* Wkv   = (const float*)d_in[4];
    const float* bkv   = (const float*)d_in[5];
    const float* Wrq   = (const float*)d_in[6];
    const float* brq   = (const float*)d_in[7];
    const float* Wrk   = (const float*)d_in[8];
    const float* brk   = (const float*)d_in[9];
    const float* Wout  = (const float*)d_in[10];
    const float* bout  = (const float*)d_in[11];
    const float* alpha = (const float*)d_in[12];
    float* out = (float*)d_out;

    bf16 *pq, *pkv, *pRq, *pRk, *ptokb, *psrcb, *ptgtb, *pWq, *pWkv, *pWrq, *pWrk, *pWout;
    float *pqr, *pkrvr, *pvals;
    cudaGetSymbolAddress((void**)&pq,    g_q);
    cudaGetSymbolAddress((void**)&pkv,   g_kv);
    cudaGetSymbolAddress((void**)&pRq,   g_Rq);
    cudaGetSymbolAddress((void**)&pRk,   g_Rk);
    cudaGetSymbolAddress((void**)&ptokb, g_tokb);
    cudaGetSymbolAddress((void**)&psrcb, g_srcb);
    cudaGetSymbolAddress((void**)&ptgtb, g_tgtb);
    cudaGetSymbolAddress((void**)&pWq,   g_Wqb);
    cudaGetSymbolAddress((void**)&pWkv,  g_Wkvb);
    cudaGetSymbolAddress((void**)&pWrq,  g_Wrqb);
    cudaGetSymbolAddress((void**)&pWrk,  g_Wrkb);
    cudaGetSymbolAddress((void**)&pWout, g_Woutb);
    cudaGetSymbolAddress((void**)&pqr,   g_qr);
    cudaGetSymbolAddress((void**)&pkrvr, g_krvr);
    cudaGetSymbolAddress((void**)&pvals, g_vals);

    zero_k<<<1024, 256>>>(pqr, pkrvr);

    const int actN4 = (BB * 256 * NN) / 4;
    cvt_k<<<(actN4 + 255) / 256, 256>>>(src, psrcb, actN4);
    cvt_k<<<(actN4 + 255) / 256, 256>>>(tgt, ptgtb, actN4);
    cvt5_k<<<512, 256>>>(Wq, Wkv, Wrq, Wrk, Wout, pWq, pWkv, pWrq, pWrk, pWout);

    const dim3 gB (NN / 128, 2, BB);   // M=256
    const dim3 gB2(NN / 128, 4, BB);   // M=512

    hgemm_k<<<gB,  256>>>(pWq,  bq,  ptgtb, pq,  nullptr, 256, 0, nullptr, nullptr);
    hgemm_k<<<gB2, 256>>>(pWkv, bkv, psrcb, pkv, nullptr, 512, 0, nullptr, nullptr);  // profiled
    hgemm_k<<<gB2, 256>>>(pWrq, brq, ptgtb, pRq, nullptr, 512, 0, nullptr, nullptr);
    hgemm_k<<<gB2, 256>>>(pWrk, brk, psrcb, pRk, nullptr, 512, 0, nullptr, nullptr);

    softmax512_k<<<dim3(BB, NN / 256), 256>>>(pRq);
    softmax512_k<<<dim3(BB, NN / 256), 256>>>(pRk);

    outer_mma_k<2><<<dim3(64, 9), 256>>>(pq,  256, 32, pRq, pqr);
    outer_mma_k<4><<<dim3(64, 9), 256>>>(pkv, 512, 64, pRk, pkrvr);

    attn_k<<<64, 64>>>(pqr, pkrvr, pvals);

    tok_k<<<dim3(64, NN / 256), 256>>>(pvals, pRq, ptokb);

    hgemm_k<<<gB, 256>>>(pWout, bout, ptokb, nullptr, out, 256, 1, tgt, alpha);
}

// round 5
// speedup vs baseline: 3.7242x; 1.4130x over previous
#include <cuda_runtime.h>
#include <cuda_bf16.h>
#include <math.h>
#include <stdint.h>

typedef __nv_bfloat16 bf16;

#define BB   8
#define NN   9216
#define KK   256

// ---------------- scratch -----------------------------------------------------
__device__ bf16  g_q  [(size_t)BB * 256 * NN];
__device__ bf16  g_kv [(size_t)BB * 512 * NN];
__device__ bf16  g_Rq [(size_t)BB * 512 * NN];
__device__ bf16  g_Rk [(size_t)BB * 512 * NN];
__device__ bf16  g_srcb[(size_t)BB * 256 * NN];
__device__ bf16  g_tgtb[(size_t)BB * 256 * NN];
__device__ bf16  g_Wqb [256 * 256];
__device__ bf16  g_Wkvb[512 * 256];
__device__ bf16  g_Wrqb[512 * 256];
__device__ bf16  g_Wrkb[512 * 256];
__device__ bf16  g_U   [(size_t)BB * 256 * 512];   // per-batch A for final gemm
__device__ float g_qr  [64 * 32 * 64];
__device__ float g_krvr[64 * 64 * 64];
__device__ float g_vals[64 * 2048];

// ---------------- prep: zero accumulators + all fp32->bf16 conversions --------
#define C_SRC  4718592
#define C_TGT  4718592
#define C_WQ   16384
#define C_WKV  32768
#define C_WR   32768
#define C_Z    98304
__global__ __launch_bounds__(256) void prep_k(
    const float* __restrict__ src, const float* __restrict__ tgt,
    const float* __restrict__ Wq, const float* __restrict__ Wkv,
    const float* __restrict__ Wrq, const float* __restrict__ Wrk,
    bf16* srcb, bf16* tgtb, bf16* wq, bf16* wkv, bf16* wrq, bf16* wrk,
    float* qr, float* krvr)
{
    long long i = (long long)blockIdx.x * 256 + threadIdx.x;
    const float* s; bf16* d; long long o;
    if (i < C_SRC)                { s = src; d = srcb; o = i; }
    else if ((i -= C_SRC) < C_TGT){ s = tgt; d = tgtb; o = i; }
    else if ((i -= C_TGT) < C_WQ) { s = Wq;  d = wq;   o = i; }
    else if ((i -= C_WQ) < C_WKV) { s = Wkv; d = wkv;  o = i; }
    else if ((i -= C_WKV) < C_WR) { s = Wrq; d = wrq;  o = i; }
    else if ((i -= C_WR) < C_WR)  { s = Wrk; d = wrk;  o = i; }
    else if ((i -= C_WR) < C_Z) {           // zero qr (32768) + krvr (65536)
        float4 z = {0.f, 0.f, 0.f, 0.f};
        if (i < 32768) *(float4*)(qr + i * 4) = z;
        else           *(float4*)(krvr + (i - 32768) * 4) = z;
        return;
    } else return;
    float4 v = *(const float4*)(s + o * 4);
    __nv_bfloat162 h0 = { __float2bfloat16(v.x), __float2bfloat16(v.y) };
    __nv_bfloat162 h1 = { __float2bfloat16(v.z), __float2bfloat16(v.w) };
    *(__nv_bfloat162*)(d + o * 4)     = h0;
    *(__nv_bfloat162*)(d + o * 4 + 2) = h1;
}

// ---------------- PTX helpers -------------------------------------------------
__device__ __forceinline__ uint32_t s2u(const void* p) {
    return (uint32_t)__cvta_generic_to_shared(p);
}
__device__ __forceinline__ void ldsm4(uint32_t& r0, uint32_t& r1, uint32_t& r2,
                                      uint32_t& r3, uint32_t a) {
    asm volatile("ldmatrix.sync.aligned.m8n8.x4.shared.b16 {%0,%1,%2,%3},[%4];\n"
        : "=r"(r0), "=r"(r1), "=r"(r2), "=r"(r3) : "r"(a));
}
__device__ __forceinline__ void ldsm4t(uint32_t& r0, uint32_t& r1, uint32_t& r2,
                                       uint32_t& r3, uint32_t a) {
    asm volatile("ldmatrix.sync.aligned.m8n8.x4.trans.shared.b16 {%0,%1,%2,%3},[%4];\n"
        : "=r"(r0), "=r"(r1), "=r"(r2), "=r"(r3) : "r"(a));
}
__device__ __forceinline__ void ldsm2(uint32_t& r0, uint32_t& r1, uint32_t a) {
    asm volatile("ldmatrix.sync.aligned.m8n8.x2.shared.b16 {%0,%1},[%2];\n"
        : "=r"(r0), "=r"(r1) : "r"(a));
}
__device__ __forceinline__ void mma16816(float* c, const uint32_t* a,
                                         uint32_t b0, uint32_t b1) {
    asm volatile(
        "mma.sync.aligned.m16n8k16.row.col.f32.bf16.bf16.f32 "
        "{%0,%1,%2,%3},{%4,%5,%6,%7},{%8,%9},{%0,%1,%2,%3};\n"
        : "+f"(c[0]), "+f"(c[1]), "+f"(c[2]), "+f"(c[3])
        : "r"(a[0]), "r"(a[1]), "r"(a[2]), "r"(a[3]), "r"(b0), "r"(b1));
}
__device__ __forceinline__ void cpasync16(uint32_t s, const void* g) {
    asm volatile("cp.async.cg.shared.global [%0], [%1], 16;\n" :: "r"(s), "l"(g));
}
__device__ __forceinline__ void cp_commit() { asm volatile("cp.async.commit_group;\n"); }
__device__ __forceinline__ void cp_wait0()  { asm volatile("cp.async.wait_group 0;\n"); }

// ---------------- bf16 tensor-core GEMM, 256x128 tile, 512 threads ------------
// Y[b](MxN) = A(MxK) @ X[b](KxN) + bias
// abatch: A advances by M*K per batch.  mode 0: bf16 out. mode 1: residual fp32.
#define APAD 40
#define BPAD 136
#define SA_ELEMS (256 * APAD)
#define SB_ELEMS (32 * BPAD)
#define HSMEM_BYTES ((2 * SA_ELEMS + 2 * SB_ELEMS) * 2)

__global__ __launch_bounds__(512) void hgemm_k(
    const bf16* __restrict__ Ab, const float* __restrict__ bias,
    const bf16* __restrict__ Xb, bf16* __restrict__ Yb, float* __restrict__ Yf,
    int M, int K, int abatch, int mode,
    const float* __restrict__ tgt, const float* __restrict__ alphap)
{
    extern __shared__ bf16 sm[];
    bf16* sA = sm;                    // [2][256*APAD]
    bf16* sB = sm + 2 * SA_ELEMS;     // [2][32*BPAD]

    const int tid  = threadIdx.x;
    const int warp = tid >> 5, lane = tid & 31;
    const int wm   = warp >> 2, wn = warp & 3;
    const int n0   = blockIdx.x * 128;
    const int m0   = blockIdx.y * 256;
    const int b    = blockIdx.z;
    const bf16* X  = Xb + (size_t)b * K * NN;
    const bf16* A  = Ab + (abatch ? (size_t)b * M * K : 0);
    const int KT   = K >> 5;

    float acc[4][4][4];
    #pragma unroll
    for (int i = 0; i < 4; i++)
        #pragma unroll
        for (int j = 0; j < 4; j++)
            #pragma unroll
            for (int k = 0; k < 4; k++) acc[i][j][k] = 0.f;

    auto issue_tile = [&](int kt, int buf) {
        bf16* a = sA + buf * SA_ELEMS;
        bf16* bb = sB + buf * SB_ELEMS;
        {   // A: 256 rows x 32 cols = 1024 chunks of 8, 2 per thread
            int c0 = tid, c1 = tid + 512;
            int r0 = c0 >> 2, k0 = (c0 & 3) * 8;
            int r1 = c1 >> 2, k1 = (c1 & 3) * 8;
            cpasync16(s2u(&a[r0 * APAD + k0]), A + (size_t)(m0 + r0) * K + kt * 32 + k0);
            cpasync16(s2u(&a[r1 * APAD + k1]), A + (size_t)(m0 + r1) * K + kt * 32 + k1);
        }
        {   // B: 32 rows x 128 cols = 512 chunks, 1 per thread
            int r = tid >> 4, c = (tid & 15) * 8;
            cpasync16(s2u(&bb[r * BPAD + c]), X + (size_t)(kt * 32 + r) * NN + n0 + c);
        }
        cp_commit();
    };

    issue_tile(0, 0);
    cp_wait0();
    __syncthreads();

    for (int kt = 0; kt < KT; kt++) {
        int cur = kt & 1;
        if (kt < KT - 1) issue_tile(kt + 1, cur ^ 1);
        bf16* a = sA + cur * SA_ELEMS;
        bf16* bb = sB + cur * SB_ELEMS;

        #pragma unroll
        for (int ks = 0; ks < 2; ks++) {
            uint32_t af[4][4];
            #pragma unroll
            for (int mt = 0; mt < 4; mt++) {
                int row = wm * 64 + mt * 16 + (lane & 15);
                int col = ks * 16 + (lane >> 4) * 8;
                ldsm4(af[mt][0], af[mt][1], af[mt][2], af[mt][3],
                      s2u(&a[row * APAD + col]));
            }
            uint32_t bf[2][4];
            #pragma unroll
            for (int ntg = 0; ntg < 2; ntg++) {
                int row = ks * 16 + (lane & 15);
                int col = wn * 32 + ntg * 16 + (lane >> 4) * 8;
                ldsm4t(bf[ntg][0], bf[ntg][1], bf[ntg][2], bf[ntg][3],
                       s2u(&bb[row * BPAD + col]));
            }
            #pragma unroll
            for (int mt = 0; mt < 4; mt++)
                #pragma unroll
                for (int nt = 0; nt < 4; nt++) {
                    int ntg = nt >> 1, half = nt & 1;
                    mma16816(acc[mt][nt], af[mt], bf[ntg][half * 2], bf[ntg][half * 2 + 1]);
                }
        }

        if (kt < KT - 1) { cp_wait0(); __syncthreads(); }
    }

    float al = (mode == 1) ? *alphap : 0.f;
    #pragma unroll
    for (int mt = 0; mt < 4; mt++) {
        #pragma unroll
        for (int rr = 0; rr < 2; rr++) {
            int m = m0 + wm * 64 + mt * 16 + rr * 8 + (lane >> 2);
            float bi = bias[m];
            size_t ybase = ((size_t)b * M + m) * NN + n0;
            #pragma unroll
            for (int nt = 0; nt < 4; nt++) {
                int n = wn * 32 + nt * 8 + (lane & 3) * 2;
                float c0 = acc[mt][nt][rr * 2 + 0] + bi;
                float c1 = acc[mt][nt][rr * 2 + 1] + bi;
                if (mode == 0) {
                    __nv_bfloat162 o = { __float2bfloat16(c0), __float2bfloat16(c1) };
                    *(__nv_bfloat162*)(Yb + ybase + n) = o;
                } else {
                    size_t tbase = ((size_t)b * 256 + m) * NN + n0;
                    float2 t = *(const float2*)(tgt + tbase + n);
                    float2 o = { t.x + al * c0, t.y + al * c1 };
                    *(float2*)(Yf + ybase + n) = o;
                }
            }
        }
    }
}

// ---------------- single-pass channel softmax (512 ch, bf16 in/out) -----------
// block 256 = 32 col-pairs x 8 channel groups; values cached in registers.
__global__ __launch_bounds__(256) void softmax1p_k(bf16* __restrict__ P)
{
    int tx = threadIdx.x & 31, ty = threadIdx.x >> 5;
    int n0 = blockIdx.y * 64 + tx * 2;
    size_t base = (size_t)blockIdx.x * 512 * NN + n0;
    __shared__ float2 red[8][33];

    uint32_t vals[64];
    float2 mx = { -1e30f, -1e30f };
    #pragma unroll 8
    for (int c = 0; c < 64; c++) {
        __nv_bfloat162 v = *(const __nv_bfloat162*)(P + base + (size_t)(ty * 64 + c) * NN);
        vals[c] = *(uint32_t*)&v;
        float2 f = __bfloat1622float2(v);
        mx.x = fmaxf(mx.x, f.x); mx.y = fmaxf(mx.y, f.y);
    }
    red[ty][tx] = mx;
    __syncthreads();
    float2 m = red[0][tx];
    #pragma unroll
    for (int g = 1; g < 8; g++) {
        m.x = fmaxf(m.x, red[g][tx].x);
        m.y = fmaxf(m.y, red[g][tx].y);
    }
    __syncthreads();

    float2 sum = { 0.f, 0.f };
    #pragma unroll 8
    for (int c = 0; c < 64; c++) {
        float2 f = __bfloat1622float2(*(__nv_bfloat162*)&vals[c]);
        float e0 = __expf(f.x - m.x), e1 = __expf(f.y - m.y);
        sum.x += e0; sum.y += e1;
        __nv_bfloat162 e = __floats2bfloat162_rn(e0, e1);
        vals[c] = *(uint32_t*)&e;
    }
    red[ty][tx] = sum;
    __syncthreads();
    float2 s = red[0][tx];
    #pragma unroll
    for (int g = 1; g < 8; g++) { s.x += red[g][tx].x; s.y += red[g][tx].y; }
    float2 inv = { 1.f / s.x, 1.f / s.y };

    #pragma unroll 8
    for (int c = 0; c < 64; c++) {
        float2 f = __bfloat1622float2(*(__nv_bfloat162*)&vals[c]);
        *(__nv_bfloat162*)(P + base + (size_t)(ty * 64 + c) * NN) =
            __floats2bfloat162_rn(f.x * inv.x, f.y * inv.y);
    }
}

// ---------------- tensor-core outer reduce ------------------------------------
template<int MR>
__global__ __launch_bounds__(256) void outer_mma_k(
    const bf16* __restrict__ A, int aC, int aH,
    const bf16* __restrict__ Rm, float* __restrict__ out)
{
    constexpr int AROWS = MR * 16;
    __shared__ bf16 sA[AROWS * 72];
    __shared__ bf16 sR[64 * 72];
    int bh = blockIdx.x, b = bh >> 3, h = bh & 7;
    const bf16* Ab = A  + ((size_t)b * aC  + h * aH) * NN;
    const bf16* Rb = Rm + ((size_t)b * 512 + h * 64) * NN;
    float* ob = out + (size_t)bh * (AROWS * 64);
    int tid = threadIdx.x, warp = tid >> 5, lane = tid & 31;

    float acc[MR][4];
    #pragma unroll
    for (int i = 0; i < MR; i++)
        #pragma unroll
        for (int j = 0; j < 4; j++) acc[i][j] = 0.f;

    int kbase = blockIdx.y * 1024;
    for (int kb = 0; kb < 16; kb++) {
        int k0 = kbase + kb * 64;
        #pragma unroll
        for (int c = tid; c < AROWS * 8; c += 256) {
            int r = c >> 3, cc = (c & 7) * 8;
            cpasync16(s2u(&sA[r * 72 + cc]), Ab + (size_t)r * NN + k0 + cc);
        }
        #pragma unroll
        for (int c = tid; c < 512; c += 256) {
            int r = c >> 3, cc = (c & 7) * 8;
            cpasync16(s2u(&sR[r * 72 + cc]), Rb + (size_t)r * NN + k0 + cc);
        }
        cp_commit(); cp_wait0();
        __syncthreads();

        int r0 = warp * 8;
        #pragma unroll
        for (int ks = 0; ks < 4; ks++) {
            uint32_t a[MR][4];
            #pragma unroll
            for (int mt = 0; mt < MR; mt++)
                ldsm4(a[mt][0], a[mt][1], a[mt][2], a[mt][3],
                      s2u(&sA[(mt * 16 + (lane & 15)) * 72 + ks * 16 + (lane >> 4) * 8]));
            uint32_t b0, b1;
            {
                int j = lane & 7, half = (lane >> 3) & 1;
                ldsm2(b0, b1, s2u(&sR[(r0 + j) * 72 + ks * 16 + half * 8]));
            }
            #pragma unroll
            for (int mt = 0; mt < MR; mt++)
                mma16816(acc[mt], a[mt], b0, b1);
        }
        __syncthreads();
    }

    int row = lane >> 2, col = warp * 8 + (lane & 3) * 2;
    #pragma unroll
    for (int mt = 0; mt < MR; mt++) {
        atomicAdd(&ob[(mt * 16 + row)     * 64 + col],     acc[mt][0]);
        atomicAdd(&ob[(mt * 16 + row)     * 64 + col + 1], acc[mt][1]);
        atomicAdd(&ob[(mt * 16 + row + 8) * 64 + col],     acc[mt][2]);
        atomicAdd(&ob[(mt * 16 + row + 8) * 64 + col + 1], acc[mt][3]);
    }
}

// ---------------- tiny attention per (b,h) ------------------------------------
__global__ __launch_bounds__(64) void attn_k(
    const float* __restrict__ qr, const float* __restrict__ krvr,
    float* __restrict__ vals)
{
    int bh = blockIdx.x; int t = threadIdx.x;
    __shared__ float sq[2048], sk[2048], sv[2048];
    const float* pq = qr   + (size_t)bh * 2048;
    const float* pk = krvr + (size_t)bh * 4096;
    const float* pv = pk + 2048;
    for (int i = t; i < 2048; i += 64) { sq[i] = pq[i]; sk[i] = pk[i]; sv[i] = pv[i]; }
    __syncthreads();

    float sc[64];
    #pragma unroll 4
    for (int k = 0; k < 64; k++) {
        float s = 0.f;
        #pragma unroll
        for (int d = 0; d < 32; d++) s += sq[d * 64 + t] * sk[d * 64 + k];
        sc[k] = s * 0.17677669529663687f;
    }
    float m = -1e30f;
    #pragma unroll
    for (int k = 0; k < 64; k++) m = fmaxf(m, sc[k]);
    float s = 0.f;
    #pragma unroll
    for (int k = 0; k < 64; k++) { sc[k] = __expf(sc[k] - m); s += sc[k]; }
    float inv = 1.f / s;
    #pragma unroll
    for (int k = 0; k < 64; k++) sc[k] *= inv;

    #pragma unroll 4
    for (int d = 0; d < 32; d++) {
        float v = 0.f;
        #pragma unroll
        for (int k = 0; k < 64; k++) v += sv[d * 64 + k] * sc[k];
        vals[(size_t)bh * 2048 + d * 64 + t] = v;
    }
}

// ---------------- U[b][m][h*64+r] = sum_d Wout[m][h*32+d] * vals[bh][d][r] ----
__global__ __launch_bounds__(256) void u_k(
    const float* __restrict__ Wout, const float* __restrict__ vals,
    bf16* __restrict__ U)
{
    int bh = blockIdx.x, b = bh >> 3, h = bh & 7;
    int m = threadIdx.x;
    __shared__ float vs[2048];
    const float* pv = vals + (size_t)bh * 2048;
    for (int i = threadIdx.x; i < 2048; i += 256) vs[i] = pv[i];
    __syncthreads();

    float acc[64];
    #pragma unroll
    for (int r = 0; r < 64; r++) acc[r] = 0.f;
    #pragma unroll 4
    for (int d = 0; d < 32; d++) {
        float w = Wout[(size_t)m * 256 + h * 32 + d];
        #pragma unroll
        for (int r = 0; r < 64; r++) acc[r] += w * vs[d * 64 + r];
    }
    bf16* up = U + ((size_t)b * 256 + m) * 512 + h * 64;
    #pragma unroll
    for (int r = 0; r < 32; r++) {
        __nv_bfloat162 o = { __float2bfloat16(acc[r * 2]), __float2bfloat16(acc[r * 2 + 1]) };
        *(__nv_bfloat162*)(up + r * 2) = o;
    }
}

// ------------------------------ launcher --------------------------------------
extern "C" void kernel_launch(void* const* d_in, const int* in_sizes, int n_in,
                              void* d_out, int out_size)
{
    const float* src   = (const float*)d_in[0];
    const float* tgt   = (const float*)d_in[1];
    const float* Wq    = (const float*)d_in[2];
    const float* bq    = (const float*)d_in[3];
    const float* Wkv   = (const float*)d_in[4];
    const float* bkv   = (const float*)d_in[5];
    const float* Wrq   = (const float*)d_in[6];
    const float* brq   = (const float*)d_in[7];
    const float* Wrk   = (const float*)d_in[8];
    const float* brk   = (const float*)d_in[9];
    const float* Wout  = (const float*)d_in[10];
    const float* bout  = (const float*)d_in[11];
    const float* alpha = (const float*)d_in[12];
    float* out = (float*)d_out;

    bf16 *pq, *pkv, *pRq, *pRk, *psrcb, *ptgtb, *pWq, *pWkv, *pWrq, *pWrk, *pU;
    float *pqr, *pkrvr, *pvals;
    cudaGetSymbolAddress((void**)&pq,    g_q);
    cudaGetSymbolAddress((void**)&pkv,   g_kv);
    cudaGetSymbolAddress((void**)&pRq,   g_Rq);
    cudaGetSymbolAddress((void**)&pRk,   g_Rk);
    cudaGetSymbolAddress((void**)&psrcb, g_srcb);
    cudaGetSymbolAddress((void**)&ptgtb, g_tgtb);
    cudaGetSymbolAddress((void**)&pWq,   g_Wqb);
    cudaGetSymbolAddress((void**)&pWkv,  g_Wkvb);
    cudaGetSymbolAddress((void**)&pWrq,  g_Wrqb);
    cudaGetSymbolAddress((void**)&pWrk,  g_Wrkb);
    cudaGetSymbolAddress((void**)&pU,    g_U);
    cudaGetSymbolAddress((void**)&pqr,   g_qr);
    cudaGetSymbolAddress((void**)&pkrvr, g_krvr);
    cudaGetSymbolAddress((void**)&pvals, g_vals);

    cudaFuncSetAttribute(hgemm_k, cudaFuncAttributeMaxDynamicSharedMemorySize, HSMEM_BYTES);

    // prep: zero + all conversions (one launch)
    {
        long long total = (long long)C_SRC + C_TGT + C_WQ + C_WKV + C_WR + C_WR + C_Z;
        int blocks = (int)((total + 255) / 256);
        prep_k<<<blocks, 256>>>(src, tgt, Wq, Wkv, Wrq, Wrk,
                                psrcb, ptgtb, pWq, pWkv, pWrq, pWrk, pqr, pkrvr);
    }

    const dim3 gB (NN / 128, 1, BB);   // M=256
    const dim3 gB2(NN / 128, 2, BB);   // M=512

    hgemm_k<<<gB,  512, HSMEM_BYTES>>>(pWq,  bq,  ptgtb, pq,  nullptr, 256, 256, 0, 0, nullptr, nullptr);
    hgemm_k<<<gB2, 512, HSMEM_BYTES>>>(pWkv, bkv, psrcb, pkv, nullptr, 512, 256, 0, 0, nullptr, nullptr);
    hgemm_k<<<gB2, 512, HSMEM_BYTES>>>(pWrq, brq, ptgtb, pRq, nullptr, 512, 256, 0, 0, nullptr, nullptr);
    hgemm_k<<<gB2, 512, HSMEM_BYTES>>>(pWrk, brk, psrcb, pRk, nullptr, 512, 256, 0, 0, nullptr, nullptr);

    softmax1p_k<<<dim3(BB, NN / 64), 256>>>(pRq);
    softmax1p_k<<<dim3(BB, NN / 64), 256>>>(pRk);

    outer_mma_k<2><<<dim3(64, 9), 256>>>(pq,  256, 32, pRq, pqr);
    outer_mma_k<4><<<dim3(64, 9), 256>>>(pkv, 512, 64, pRk, pkrvr);

    attn_k<<<64, 64>>>(pqr, pkrvr, pvals);

    u_k<<<64, 256>>>(Wout, pvals, pU);

    // out = tgt + alpha * (U @ Rq + bout)   [K = 512, batched A]
    hgemm_k<<<gB, 512, HSMEM_BYTES>>>(pU, bout, pRq, nullptr, out, 256, 512, 1, 1, tgt, alpha);
}

// round 6
// speedup vs baseline: 4.1331x; 1.1098x over previous
#include <cuda_runtime.h>
#include <cuda_bf16.h>
#include <math.h>
#include <stdint.h>

typedef __nv_bfloat16 bf16;

#define BB   8
#define NN   9216
#define KK   256

// ---------------- scratch -----------------------------------------------------
__device__ bf16  g_q  [(size_t)BB * 256 * NN];
__device__ bf16  g_kv [(size_t)BB * 512 * NN];
__device__ bf16  g_Rq [(size_t)BB * 512 * NN];
__device__ bf16  g_Rk [(size_t)BB * 512 * NN];
__device__ bf16  g_srcb[(size_t)BB * 256 * NN];
__device__ bf16  g_tgtb[(size_t)BB * 256 * NN];
__device__ bf16  g_Wqb [256 * 256];
__device__ bf16  g_Wkvb[512 * 256];
__device__ bf16  g_Wrqb[512 * 256];
__device__ bf16  g_Wrkb[512 * 256];
__device__ bf16  g_U   [(size_t)BB * 256 * 512];
__device__ float g_qr  [64 * 32 * 64];
__device__ float g_krvr[64 * 64 * 64];
__device__ float g_vals[64 * 2048];

// ---------------- prep: zero accumulators + all fp32->bf16 conversions --------
#define C_SRC  4718592
#define C_TGT  4718592
#define C_WQ   16384
#define C_WKV  32768
#define C_WR   32768
#define C_Z    98304
__global__ __launch_bounds__(256) void prep_k(
    const float* __restrict__ src, const float* __restrict__ tgt,
    const float* __restrict__ Wq, const float* __restrict__ Wkv,
    const float* __restrict__ Wrq, const float* __restrict__ Wrk,
    bf16* srcb, bf16* tgtb, bf16* wq, bf16* wkv, bf16* wrq, bf16* wrk,
    float* qr, float* krvr)
{
    long long i = (long long)blockIdx.x * 256 + threadIdx.x;
    const float* s; bf16* d; long long o;
    if (i < C_SRC)                { s = src; d = srcb; o = i; }
    else if ((i -= C_SRC) < C_TGT){ s = tgt; d = tgtb; o = i; }
    else if ((i -= C_TGT) < C_WQ) { s = Wq;  d = wq;   o = i; }
    else if ((i -= C_WQ) < C_WKV) { s = Wkv; d = wkv;  o = i; }
    else if ((i -= C_WKV) < C_WR) { s = Wrq; d = wrq;  o = i; }
    else if ((i -= C_WR) < C_WR)  { s = Wrk; d = wrk;  o = i; }
    else if ((i -= C_WR) < C_Z) {
        float4 z = {0.f, 0.f, 0.f, 0.f};
        if (i < 32768) *(float4*)(qr + i * 4) = z;
        else           *(float4*)(krvr + (i - 32768) * 4) = z;
        return;
    } else return;
    float4 v = *(const float4*)(s + o * 4);
    __nv_bfloat162 h0 = { __float2bfloat16(v.x), __float2bfloat16(v.y) };
    __nv_bfloat162 h1 = { __float2bfloat16(v.z), __float2bfloat16(v.w) };
    *(__nv_bfloat162*)(d + o * 4)     = h0;
    *(__nv_bfloat162*)(d + o * 4 + 2) = h1;
}

// ---------------- PTX helpers -------------------------------------------------
__device__ __forceinline__ uint32_t s2u(const void* p) {
    return (uint32_t)__cvta_generic_to_shared(p);
}
__device__ __forceinline__ void ldsm4(uint32_t& r0, uint32_t& r1, uint32_t& r2,
                                      uint32_t& r3, uint32_t a) {
    asm volatile("ldmatrix.sync.aligned.m8n8.x4.shared.b16 {%0,%1,%2,%3},[%4];\n"
        : "=r"(r0), "=r"(r1), "=r"(r2), "=r"(r3) : "r"(a));
}
__device__ __forceinline__ void ldsm4t(uint32_t& r0, uint32_t& r1, uint32_t& r2,
                                       uint32_t& r3, uint32_t a) {
    asm volatile("ldmatrix.sync.aligned.m8n8.x4.trans.shared.b16 {%0,%1,%2,%3},[%4];\n"
        : "=r"(r0), "=r"(r1), "=r"(r2), "=r"(r3) : "r"(a));
}
__device__ __forceinline__ void ldsm2(uint32_t& r0, uint32_t& r1, uint32_t a) {
    asm volatile("ldmatrix.sync.aligned.m8n8.x2.shared.b16 {%0,%1},[%2];\n"
        : "=r"(r0), "=r"(r1) : "r"(a));
}
__device__ __forceinline__ void mma16816(float* c, const uint32_t* a,
                                         uint32_t b0, uint32_t b1) {
    asm volatile(
        "mma.sync.aligned.m16n8k16.row.col.f32.bf16.bf16.f32 "
        "{%0,%1,%2,%3},{%4,%5,%6,%7},{%8,%9},{%0,%1,%2,%3};\n"
        : "+f"(c[0]), "+f"(c[1]), "+f"(c[2]), "+f"(c[3])
        : "r"(a[0]), "r"(a[1]), "r"(a[2]), "r"(a[3]), "r"(b0), "r"(b1));
}
__device__ __forceinline__ void cpasync16(uint32_t s, const void* g) {
    asm volatile("cp.async.cg.shared.global [%0], [%1], 16;\n" :: "r"(s), "l"(g));
}
__device__ __forceinline__ void cp_commit() { asm volatile("cp.async.commit_group;\n"); }
__device__ __forceinline__ void cp_wait0()  { asm volatile("cp.async.wait_group 0;\n"); }
__device__ __forceinline__ void cp_wait1()  { asm volatile("cp.async.wait_group 1;\n"); }

// ---------------- bf16 tensor-core GEMM, 256x128 tile, BK=64, 3-stage ---------
// Y[b](MxN) = A(MxK) @ X[b](KxN) + bias
#define APAD 72     // A smem row stride (BK 64 + 8)
#define BPAD 136    // B smem row stride (128 + 8)
#define SA_ELEMS (256 * APAD)
#define SB_ELEMS (64 * BPAD)
#define NSTAGE 3
#define HSMEM_BYTES (NSTAGE * (SA_ELEMS + SB_ELEMS) * 2)

__global__ __launch_bounds__(512) void hgemm_k(
    const bf16* __restrict__ Ab, const float* __restrict__ bias,
    const bf16* __restrict__ Xb, bf16* __restrict__ Yb, float* __restrict__ Yf,
    int M, int K, int abatch, int mode,
    const float* __restrict__ tgt, const float* __restrict__ alphap)
{
    extern __shared__ bf16 sm[];
    bf16* sA = sm;                         // [NSTAGE][256*APAD]
    bf16* sB = sm + NSTAGE * SA_ELEMS;     // [NSTAGE][64*BPAD]

    const int tid  = threadIdx.x;
    const int warp = tid >> 5, lane = tid & 31;
    const int wm   = warp >> 2, wn = warp & 3;
    const int n0   = blockIdx.x * 128;
    const int m0   = blockIdx.y * 256;
    const int b    = blockIdx.z;
    const bf16* X  = Xb + (size_t)b * K * NN;
    const bf16* A  = Ab + (abatch ? (size_t)b * M * K : 0);
    const int KT   = K >> 6;               // number of BK=64 tiles

    float acc[4][4][4];
    #pragma unroll
    for (int i = 0; i < 4; i++)
        #pragma unroll
        for (int j = 0; j < 4; j++)
            #pragma unroll
            for (int k = 0; k < 4; k++) acc[i][j][k] = 0.f;

    auto issue_tile = [&](int kt, int buf) {
        bf16* a  = sA + buf * SA_ELEMS;
        bf16* bb = sB + buf * SB_ELEMS;
        // A: 256 rows x 64 cols = 2048 chunks of 8 elems; 4 per thread
        #pragma unroll
        for (int i = 0; i < 4; i++) {
            int c = tid + i * 512;
            int r = c >> 3, k = (c & 7) * 8;
            cpasync16(s2u(&a[r * APAD + k]), A + (size_t)(m0 + r) * K + kt * 64 + k);
        }
        // B: 64 rows x 128 cols = 1024 chunks; 2 per thread
        #pragma unroll
        for (int i = 0; i < 2; i++) {
            int c = tid + i * 512;
            int r = c >> 4, cc = (c & 15) * 8;
            cpasync16(s2u(&bb[r * BPAD + cc]), X + (size_t)(kt * 64 + r) * NN + n0 + cc);
        }
        cp_commit();
    };

    issue_tile(0, 0);
    if (KT > 1) issue_tile(1, 1);
    cp_wait1();           // tile 0 ready (tile 1 may be in flight)
    __syncthreads();

    for (int kt = 0; kt < KT; kt++) {
        int cur = kt % NSTAGE;
        bf16* a  = sA + cur * SA_ELEMS;
        bf16* bb = sB + cur * SB_ELEMS;

        #pragma unroll
        for (int ks = 0; ks < 4; ks++) {
            uint32_t af[4][4];
            #pragma unroll
            for (int mt = 0; mt < 4; mt++) {
                int row = wm * 64 + mt * 16 + (lane & 15);
                int col = ks * 16 + (lane >> 4) * 8;
                ldsm4(af[mt][0], af[mt][1], af[mt][2], af[mt][3],
                      s2u(&a[row * APAD + col]));
            }
            uint32_t bfr[2][4];
            #pragma unroll
            for (int ntg = 0; ntg < 2; ntg++) {
                int row = ks * 16 + (lane & 15);
                int col = wn * 32 + ntg * 16 + (lane >> 4) * 8;
                ldsm4t(bfr[ntg][0], bfr[ntg][1], bfr[ntg][2], bfr[ntg][3],
                       s2u(&bb[row * BPAD + col]));
            }
            #pragma unroll
            for (int mt = 0; mt < 4; mt++)
                #pragma unroll
                for (int nt = 0; nt < 4; nt++) {
                    int ntg = nt >> 1, half = nt & 1;
                    mma16816(acc[mt][nt], af[mt], bfr[ntg][half * 2], bfr[ntg][half * 2 + 1]);
                }
        }

        if (kt + 2 < KT) {
            issue_tile(kt + 2, (kt + 2) % NSTAGE);
            cp_wait1();            // tile kt+1 arrived; kt+2 still flying
            __syncthreads();
        } else if (kt + 1 < KT) {
            cp_wait0();            // last tile must be fully in
            __syncthreads();
        }
    }

    float al = (mode == 1) ? *alphap : 0.f;
    #pragma unroll
    for (int mt = 0; mt < 4; mt++) {
        #pragma unroll
        for (int rr = 0; rr < 2; rr++) {
            int m = m0 + wm * 64 + mt * 16 + rr * 8 + (lane >> 2);
            float bi = bias[m];
            size_t ybase = ((size_t)b * M + m) * NN + n0;
            #pragma unroll
            for (int nt = 0; nt < 4; nt++) {
                int n = wn * 32 + nt * 8 + (lane & 3) * 2;
                float c0 = acc[mt][nt][rr * 2 + 0] + bi;
                float c1 = acc[mt][nt][rr * 2 + 1] + bi;
                if (mode == 0) {
                    __nv_bfloat162 o = { __float2bfloat16(c0), __float2bfloat16(c1) };
                    *(__nv_bfloat162*)(Yb + ybase + n) = o;
                } else {
                    size_t tbase = ((size_t)b * 256 + m) * NN + n0;
                    float2 t = *(const float2*)(tgt + tbase + n);
                    float2 o = { t.x + al * c0, t.y + al * c1 };
                    *(float2*)(Yf + ybase + n) = o;
                }
            }
        }
    }
}

// ---------------- single-pass channel softmax (512 ch, bf16 in/out) -----------
__global__ __launch_bounds__(256) void softmax1p_k(bf16* __restrict__ P)
{
    int tx = threadIdx.x & 31, ty = threadIdx.x >> 5;
    int n0 = blockIdx.y * 64 + tx * 2;
    size_t base = (size_t)blockIdx.x * 512 * NN + n0;
    __shared__ float2 red[8][33];

    uint32_t vals[64];
    float2 mx = { -1e30f, -1e30f };
    #pragma unroll 8
    for (int c = 0; c < 64; c++) {
        __nv_bfloat162 v = *(const __nv_bfloat162*)(P + base + (size_t)(ty * 64 + c) * NN);
        vals[c] = *(uint32_t*)&v;
        float2 f = __bfloat1622float2(v);
        mx.x = fmaxf(mx.x, f.x); mx.y = fmaxf(mx.y, f.y);
    }
    red[ty][tx] = mx;
    __syncthreads();
    float2 m = red[0][tx];
    #pragma unroll
    for (int g = 1; g < 8; g++) {
        m.x = fmaxf(m.x, red[g][tx].x);
        m.y = fmaxf(m.y, red[g][tx].y);
    }
    __syncthreads();

    float2 sum = { 0.f, 0.f };
    #pragma unroll 8
    for (int c = 0; c < 64; c++) {
        float2 f = __bfloat1622float2(*(__nv_bfloat162*)&vals[c]);
        float e0 = __expf(f.x - m.x), e1 = __expf(f.y - m.y);
        sum.x += e0; sum.y += e1;
        __nv_bfloat162 e = __floats2bfloat162_rn(e0, e1);
        vals[c] = *(uint32_t*)&e;
    }
    red[ty][tx] = sum;
    __syncthreads();
    float2 s = red[0][tx];
    #pragma unroll
    for (int g = 1; g < 8; g++) { s.x += red[g][tx].x; s.y += red[g][tx].y; }
    float2 inv = { 1.f / s.x, 1.f / s.y };

    #pragma unroll 8
    for (int c = 0; c < 64; c++) {
        float2 f = __bfloat1622float2(*(__nv_bfloat162*)&vals[c]);
        *(__nv_bfloat162*)(P + base + (size_t)(ty * 64 + c) * NN) =
            __floats2bfloat162_rn(f.x * inv.x, f.y * inv.y);
    }
}

// ---------------- tensor-core outer reduce ------------------------------------
template<int MR>
__global__ __launch_bounds__(256) void outer_mma_k(
    const bf16* __restrict__ A, int aC, int aH,
    const bf16* __restrict__ Rm, float* __restrict__ out)
{
    constexpr int AROWS = MR * 16;
    __shared__ bf16 sA[AROWS * 72];
    __shared__ bf16 sR[64 * 72];
    int bh = blockIdx.x, b = bh >> 3, h = bh & 7;
    const bf16* Ab = A  + ((size_t)b * aC  + h * aH) * NN;
    const bf16* Rb = Rm + ((size_t)b * 512 + h * 64) * NN;
    float* ob = out + (size_t)bh * (AROWS * 64);
    int tid = threadIdx.x, warp = tid >> 5, lane = tid & 31;

    float acc[MR][4];
    #pragma unroll
    for (int i = 0; i < MR; i++)
        #pragma unroll
        for (int j = 0; j < 4; j++) acc[i][j] = 0.f;

    int kbase = blockIdx.y * 1024;
    for (int kb = 0; kb < 16; kb++) {
        int k0 = kbase + kb * 64;
        #pragma unroll
        for (int c = tid; c < AROWS * 8; c += 256) {
            int r = c >> 3, cc = (c & 7) * 8;
            cpasync16(s2u(&sA[r * 72 + cc]), Ab + (size_t)r * NN + k0 + cc);
        }
        #pragma unroll
        for (int c = tid; c < 512; c += 256) {
            int r = c >> 3, cc = (c & 7) * 8;
            cpasync16(s2u(&sR[r * 72 + cc]), Rb + (size_t)r * NN + k0 + cc);
        }
        cp_commit(); cp_wait0();
        __syncthreads();

        int r0 = warp * 8;
        #pragma unroll
        for (int ks = 0; ks < 4; ks++) {
            uint32_t a[MR][4];
            #pragma unroll
            for (int mt = 0; mt < MR; mt++)
                ldsm4(a[mt][0], a[mt][1], a[mt][2], a[mt][3],
                      s2u(&sA[(mt * 16 + (lane & 15)) * 72 + ks * 16 + (lane >> 4) * 8]));
            uint32_t b0, b1;
            {
                int j = lane & 7, half = (lane >> 3) & 1;
                ldsm2(b0, b1, s2u(&sR[(r0 + j) * 72 + ks * 16 + half * 8]));
            }
            #pragma unroll
            for (int mt = 0; mt < MR; mt++)
                mma16816(acc[mt], a[mt], b0, b1);
        }
        __syncthreads();
    }

    int row = lane >> 2, col = warp * 8 + (lane & 3) * 2;
    #pragma unroll
    for (int mt = 0; mt < MR; mt++) {
        atomicAdd(&ob[(mt * 16 + row)     * 64 + col],     acc[mt][0]);
        atomicAdd(&ob[(mt * 16 + row)     * 64 + col + 1], acc[mt][1]);
        atomicAdd(&ob[(mt * 16 + row + 8) * 64 + col],     acc[mt][2]);
        atomicAdd(&ob[(mt * 16 + row + 8) * 64 + col + 1], acc[mt][3]);
    }
}

// ---------------- tiny attention per (b,h) ------------------------------------
__global__ __launch_bounds__(64) void attn_k(
    const float* __restrict__ qr, const float* __restrict__ krvr,
    float* __restrict__ vals)
{
    int bh = blockIdx.x; int t = threadIdx.x;
    __shared__ float sq[2048], sk[2048], sv[2048];
    const float* pq = qr   + (size_t)bh * 2048;
    const float* pk = krvr + (size_t)bh * 4096;
    const float* pv = pk + 2048;
    for (int i = t; i < 2048; i += 64) { sq[i] = pq[i]; sk[i] = pk[i]; sv[i] = pv[i]; }
    __syncthreads();

    float sc[64];
    #pragma unroll 4
    for (int k = 0; k < 64; k++) {
        float s = 0.f;
        #pragma unroll
        for (int d = 0; d < 32; d++) s += sq[d * 64 + t] * sk[d * 64 + k];
        sc[k] = s * 0.17677669529663687f;
    }
    float m = -1e30f;
    #pragma unroll
    for (int k = 0; k < 64; k++) m = fmaxf(m, sc[k]);
    float s = 0.f;
    #pragma unroll
    for (int k = 0; k < 64; k++) { sc[k] = __expf(sc[k] - m); s += sc[k]; }
    float inv = 1.f / s;
    #pragma unroll
    for (int k = 0; k < 64; k++) sc[k] *= inv;

    #pragma unroll 4
    for (int d = 0; d < 32; d++) {
        float v = 0.f;
        #pragma unroll
        for (int k = 0; k < 64; k++) v += sv[d * 64 + k] * sc[k];
        vals[(size_t)bh * 2048 + d * 64 + t] = v;
    }
}

// ---------------- U[b][m][h*64+r] = sum_d Wout[m][h*32+d] * vals[bh][d][r] ----
__global__ __launch_bounds__(256) void u_k(
    const float* __restrict__ Wout, const float* __restrict__ vals,
    bf16* __restrict__ U)
{
    int bh = blockIdx.x, b = bh >> 3, h = bh & 7;
    int m = threadIdx.x;
    __shared__ float vs[2048];
    const float* pv = vals + (size_t)bh * 2048;
    for (int i = threadIdx.x; i < 2048; i += 256) vs[i] = pv[i];
    __syncthreads();

    float acc[64];
    #pragma unroll
    for (int r = 0; r < 64; r++) acc[r] = 0.f;
    #pragma unroll 4
    for (int d = 0; d < 32; d++) {
        float w = Wout[(size_t)m * 256 + h * 32 + d];
        #pragma unroll
        for (int r = 0; r < 64; r++) acc[r] += w * vs[d * 64 + r];
    }
    bf16* up = U + ((size_t)b * 256 + m) * 512 + h * 64;
    #pragma unroll
    for (int r = 0; r < 32; r++) {
        __nv_bfloat162 o = { __float2bfloat16(acc[r * 2]), __float2bfloat16(acc[r * 2 + 1]) };
        *(__nv_bfloat162*)(up + r * 2) = o;
    }
}

// ------------------------------ launcher --------------------------------------
extern "C" void kernel_launch(void* const* d_in, const int* in_sizes, int n_in,
                              void* d_out, int out_size)
{
    const float* src   = (const float*)d_in[0];
    const float* tgt   = (const float*)d_in[1];
    const float* Wq    = (const float*)d_in[2];
    const float* bq    = (const float*)d_in[3];
    const float* Wkv   = (const float*)d_in[4];
    const float* bkv   = (const float*)d_in[5];
    const float* Wrq   = (const float*)d_in[6];
    const float* brq   = (const float*)d_in[7];
    const float* Wrk   = (const float*)d_in[8];
    const float* brk   = (const float*)d_in[9];
    const float* Wout  = (const float*)d_in[10];
    const float* bout  = (const float*)d_in[11];
    const float* alpha = (const float*)d_in[12];
    float* out = (float*)d_out;

    bf16 *pq, *pkv, *pRq, *pRk, *psrcb, *ptgtb, *pWq, *pWkv, *pWrq, *pWrk, *pU;
    float *pqr, *pkrvr, *pvals;
    cudaGetSymbolAddress((void**)&pq,    g_q);
    cudaGetSymbolAddress((void**)&pkv,   g_kv);
    cudaGetSymbolAddress((void**)&pRq,   g_Rq);
    cudaGetSymbolAddress((void**)&pRk,   g_Rk);
    cudaGetSymbolAddress((void**)&psrcb, g_srcb);
    cudaGetSymbolAddress((void**)&ptgtb, g_tgtb);
    cudaGetSymbolAddress((void**)&pWq,   g_Wqb);
    cudaGetSymbolAddress((void**)&pWkv,  g_Wkvb);
    cudaGetSymbolAddress((void**)&pWrq,  g_Wrqb);
    cudaGetSymbolAddress((void**)&pWrk,  g_Wrkb);
    cudaGetSymbolAddress((void**)&pU,    g_U);
    cudaGetSymbolAddress((void**)&pqr,   g_qr);
    cudaGetSymbolAddress((void**)&pkrvr, g_krvr);
    cudaGetSymbolAddress((void**)&pvals, g_vals);

    cudaFuncSetAttribute(hgemm_k, cudaFuncAttributeMaxDynamicSharedMemorySize, HSMEM_BYTES);

    {
        long long total = (long long)C_SRC + C_TGT + C_WQ + C_WKV + C_WR + C_WR + C_Z;
        int blocks = (int)((total + 255) / 256);
        prep_k<<<blocks, 256>>>(src, tgt, Wq, Wkv, Wrq, Wrk,
                                psrcb, ptgtb, pWq, pWkv, pWrq, pWrk, pqr, pkrvr);
    }

    const dim3 gB (NN / 128, 1, BB);   // M=256
    const dim3 gB2(NN / 128, 2, BB);   // M=512

    hgemm_k<<<gB,  512, HSMEM_BYTES>>>(pWq,  bq,  ptgtb, pq,  nullptr, 256, 256, 0, 0, nullptr, nullptr);
    hgemm_k<<<gB2, 512, HSMEM_BYTES>>>(pWkv, bkv, psrcb, pkv, nullptr, 512, 256, 0, 0, nullptr, nullptr);
    hgemm_k<<<gB2, 512, HSMEM_BYTES>>>(pWrq, brq, ptgtb, pRq, nullptr, 512, 256, 0, 0, nullptr, nullptr);
    hgemm_k<<<gB2, 512, HSMEM_BYTES>>>(pWrk, brk, psrcb, pRk, nullptr, 512, 256, 0, 0, nullptr, nullptr);

    softmax1p_k<<<dim3(BB, NN / 64), 256>>>(pRq);
    softmax1p_k<<<dim3(BB, NN / 64), 256>>>(pRk);

    outer_mma_k<2><<<dim3(64, 9), 256>>>(pq,  256, 32, pRq, pqr);
    outer_mma_k<4><<<dim3(64, 9), 256>>>(pkv, 512, 64, pRk, pkrvr);

    attn_k<<<64, 64>>>(pqr, pkrvr, pvals);

    u_k<<<64, 256>>>(Wout, pvals, pU);

    hgemm_k<<<gB, 512, HSMEM_BYTES>>>(pU, bout, pRq, nullptr, out, 256, 512, 1, 1, tgt, alpha);
}

// round 8
// speedup vs baseline: 4.2879x; 1.0375x over previous
#include <cuda_runtime.h>
#include <cuda_bf16.h>
#include <math.h>
#include <stdint.h>

typedef __nv_bfloat16 bf16;

#define BB   8
#define NN   9216
#define KK   256

// ---------------- scratch -----------------------------------------------------
__device__ bf16  g_q  [(size_t)BB * 256 * NN];
__device__ bf16  g_kv [(size_t)BB * 512 * NN];
__device__ bf16  g_Rq [(size_t)BB * 512 * NN];
__device__ bf16  g_Rk [(size_t)BB * 512 * NN];
__device__ bf16  g_srcb[(size_t)BB * 256 * NN];
__device__ bf16  g_tgtb[(size_t)BB * 256 * NN];
__device__ bf16  g_Wqb [256 * 256];
__device__ bf16  g_Wkvb[512 * 256];
__device__ bf16  g_Wrqb[512 * 256];
__device__ bf16  g_Wrkb[512 * 256];
__device__ bf16  g_U   [(size_t)BB * 256 * 512];
__device__ float g_qr  [64 * 32 * 64];
__device__ float g_krvr[64 * 64 * 64];
__device__ float g_vals[64 * 2048];

// ---------------- prep: zero accumulators + all fp32->bf16 conversions --------
#define C_SRC  4718592
#define C_TGT  4718592
#define C_WQ   16384
#define C_WKV  32768
#define C_WR   32768
#define C_Z    98304
__global__ __launch_bounds__(256) void prep_k(
    const float* __restrict__ src, const float* __restrict__ tgt,
    const float* __restrict__ Wq, const float* __restrict__ Wkv,
    const float* __restrict__ Wrq, const float* __restrict__ Wrk,
    bf16* srcb, bf16* tgtb, bf16* wq, bf16* wkv, bf16* wrq, bf16* wrk,
    float* qr, float* krvr)
{
    long long i = (long long)blockIdx.x * 256 + threadIdx.x;
    const float* s; bf16* d; long long o;
    if (i < C_SRC)                { s = src; d = srcb; o = i; }
    else if ((i -= C_SRC) < C_TGT){ s = tgt; d = tgtb; o = i; }
    else if ((i -= C_TGT) < C_WQ) { s = Wq;  d = wq;   o = i; }
    else if ((i -= C_WQ) < C_WKV) { s = Wkv; d = wkv;  o = i; }
    else if ((i -= C_WKV) < C_WR) { s = Wrq; d = wrq;  o = i; }
    else if ((i -= C_WR) < C_WR)  { s = Wrk; d = wrk;  o = i; }
    else if ((i -= C_WR) < C_Z) {
        float4 z = {0.f, 0.f, 0.f, 0.f};
        if (i < 32768) *(float4*)(qr + i * 4) = z;
        else           *(float4*)(krvr + (i - 32768) * 4) = z;
        return;
    } else return;
    float4 v = *(const float4*)(s + o * 4);
    __nv_bfloat162 h0 = { __float2bfloat16(v.x), __float2bfloat16(v.y) };
    __nv_bfloat162 h1 = { __float2bfloat16(v.z), __float2bfloat16(v.w) };
    *(__nv_bfloat162*)(d + o * 4)     = h0;
    *(__nv_bfloat162*)(d + o * 4 + 2) = h1;
}

// ---------------- PTX helpers -------------------------------------------------
__device__ __forceinline__ uint32_t s2u(const void* p) {
    return (uint32_t)__cvta_generic_to_shared(p);
}
__device__ __forceinline__ void ldsm4(uint32_t& r0, uint32_t& r1, uint32_t& r2,
                                      uint32_t& r3, uint32_t a) {
    asm volatile("ldmatrix.sync.aligned.m8n8.x4.shared.b16 {%0,%1,%2,%3},[%4];\n"
        : "=r"(r0), "=r"(r1), "=r"(r2), "=r"(r3) : "r"(a));
}
__device__ __forceinline__ void ldsm4t(uint32_t& r0, uint32_t& r1, uint32_t& r2,
                                       uint32_t& r3, uint32_t a) {
    asm volatile("ldmatrix.sync.aligned.m8n8.x4.trans.shared.b16 {%0,%1,%2,%3},[%4];\n"
        : "=r"(r0), "=r"(r1), "=r"(r2), "=r"(r3) : "r"(a));
}
__device__ __forceinline__ void ldsm2(uint32_t& r0, uint32_t& r1, uint32_t a) {
    asm volatile("ldmatrix.sync.aligned.m8n8.x2.shared.b16 {%0,%1},[%2];\n"
        : "=r"(r0), "=r"(r1) : "r"(a));
}
__device__ __forceinline__ void mma16816(float* c, const uint32_t* a,
                                         uint32_t b0, uint32_t b1) {
    asm volatile(
        "mma.sync.aligned.m16n8k16.row.col.f32.bf16.bf16.f32 "
        "{%0,%1,%2,%3},{%4,%5,%6,%7},{%8,%9},{%0,%1,%2,%3};\n"
        : "+f"(c[0]), "+f"(c[1]), "+f"(c[2]), "+f"(c[3])
        : "r"(a[0]), "r"(a[1]), "r"(a[2]), "r"(a[3]), "r"(b0), "r"(b1));
}
__device__ __forceinline__ void cpasync16(uint32_t s, const void* g) {
    asm volatile("cp.async.cg.shared.global [%0], [%1], 16;\n" :: "r"(s), "l"(g));
}
__device__ __forceinline__ void cp_commit() { asm volatile("cp.async.commit_group;\n"); }
__device__ __forceinline__ void cp_wait0()  { asm volatile("cp.async.wait_group 0;\n"); }
__device__ __forceinline__ void cp_wait1()  { asm volatile("cp.async.wait_group 1;\n"); }

// ---------------- bf16 HMMA GEMM, 128x128 tile, BK=64, 3-stage, 2 CTAs/SM -----
// Y[b](MxN) = A(MxK) @ X[b](KxN) + bias
#define APAD 72     // A smem row stride (BK 64 + 8)
#define BPAD 136    // B smem row stride (128 + 8)
#define SA_ELEMS (128 * APAD)
#define SB_ELEMS (64 * BPAD)
#define NSTAGE 3
#define HSMEM_BYTES (NSTAGE * (SA_ELEMS + SB_ELEMS) * 2)   // 107520

__global__ __launch_bounds__(256, 2) void hgemm_k(
    const bf16* __restrict__ Ab, const float* __restrict__ bias,
    const bf16* __restrict__ Xb, bf16* __restrict__ Yb, float* __restrict__ Yf,
    int M, int K, int abatch, int mode,
    const float* __restrict__ tgt, const float* __restrict__ alphap)
{
    extern __shared__ bf16 sm[];
    bf16* sA = sm;                         // [NSTAGE][128*APAD]
    bf16* sB = sm + NSTAGE * SA_ELEMS;     // [NSTAGE][64*BPAD]

    const int tid  = threadIdx.x;
    const int warp = tid >> 5, lane = tid & 31;
    const int wm   = warp >> 2, wn = warp & 3;    // 2 x 4 warps, tile 64x32
    const int n0   = blockIdx.x * 128;
    const int m0   = blockIdx.y * 128;
    const int b    = blockIdx.z;
    const bf16* X  = Xb + (size_t)b * K * NN;
    const bf16* A  = Ab + (abatch ? (size_t)b * M * K : 0);
    const int KT   = K >> 6;

    float acc[4][4][4];
    #pragma unroll
    for (int i = 0; i < 4; i++)
        #pragma unroll
        for (int j = 0; j < 4; j++)
            #pragma unroll
            for (int k = 0; k < 4; k++) acc[i][j][k] = 0.f;

    auto issue_tile = [&](int kt, int buf) {
        bf16* a  = sA + buf * SA_ELEMS;
        bf16* bb = sB + buf * SB_ELEMS;
        // A: 128 rows x 64 cols = 1024 chunks of 8 elems; 4 per thread
        #pragma unroll
        for (int i = 0; i < 4; i++) {
            int c = tid + i * 256;
            int r = c >> 3, k = (c & 7) * 8;
            cpasync16(s2u(&a[r * APAD + k]), A + (size_t)(m0 + r) * K + kt * 64 + k);
        }
        // B: 64 rows x 128 cols = 1024 chunks; 4 per thread
        #pragma unroll
        for (int i = 0; i < 4; i++) {
            int c = tid + i * 256;
            int r = c >> 4, cc = (c & 15) * 8;
            cpasync16(s2u(&bb[r * BPAD + cc]), X + (size_t)(kt * 64 + r) * NN + n0 + cc);
        }
        cp_commit();
    };

    issue_tile(0, 0);
    if (KT > 1) issue_tile(1, 1);
    cp_wait1();
    __syncthreads();

    for (int kt = 0; kt < KT; kt++) {
        int cur = kt % NSTAGE;
        bf16* a  = sA + cur * SA_ELEMS;
        bf16* bb = sB + cur * SB_ELEMS;

        #pragma unroll
        for (int ks = 0; ks < 4; ks++) {
            uint32_t af[4][4];
            #pragma unroll
            for (int mt = 0; mt < 4; mt++) {
                int row = wm * 64 + mt * 16 + (lane & 15);
                int col = ks * 16 + (lane >> 4) * 8;
                ldsm4(af[mt][0], af[mt][1], af[mt][2], af[mt][3],
                      s2u(&a[row * APAD + col]));
            }
            uint32_t bfr[2][4];
            #pragma unroll
            for (int ntg = 0; ntg < 2; ntg++) {
                int row = ks * 16 + (lane & 15);
                int col = wn * 32 + ntg * 16 + (lane >> 4) * 8;
                ldsm4t(bfr[ntg][0], bfr[ntg][1], bfr[ntg][2], bfr[ntg][3],
                       s2u(&bb[row * BPAD + col]));
            }
            #pragma unroll
            for (int mt = 0; mt < 4; mt++)
                #pragma unroll
                for (int nt = 0; nt < 4; nt++) {
                    int ntg = nt >> 1, half = nt & 1;
                    mma16816(acc[mt][nt], af[mt], bfr[ntg][half * 2], bfr[ntg][half * 2 + 1]);
                }
        }

        if (kt + 2 < KT) {
            issue_tile(kt + 2, (kt + 2) % NSTAGE);
            cp_wait1();
            __syncthreads();
        } else if (kt + 1 < KT) {
            cp_wait0();
            __syncthreads();
        }
    }

    float al = (mode == 1) ? *alphap : 0.f;
    #pragma unroll
    for (int mt = 0; mt < 4; mt++) {
        #pragma unroll
        for (int rr = 0; rr < 2; rr++) {
            int m = m0 + wm * 64 + mt * 16 + rr * 8 + (lane >> 2);
            float bi = bias[m];
            size_t ybase = ((size_t)b * M + m) * NN + n0;
            #pragma unroll
            for (int nt = 0; nt < 4; nt++) {
                int n = wn * 32 + nt * 8 + (lane & 3) * 2;
                float c0 = acc[mt][nt][rr * 2 + 0] + bi;
                float c1 = acc[mt][nt][rr * 2 + 1] + bi;
                if (mode == 0) {
                    __nv_bfloat162 o = { __float2bfloat16(c0), __float2bfloat16(c1) };
                    *(__nv_bfloat162*)(Yb + ybase + n) = o;
                } else {
                    size_t tbase = ((size_t)b * 256 + m) * NN + n0;
                    float2 t = *(const float2*)(tgt + tbase + n);
                    float2 o = { t.x + al * c0, t.y + al * c1 };
                    *(float2*)(Yf + ybase + n) = o;
                }
            }
        }
    }
}

// ---------------- single-pass channel softmax (512 ch, bf16 in/out) -----------
__global__ __launch_bounds__(256) void softmax1p_k(bf16* __restrict__ P)
{
    int tx = threadIdx.x & 31, ty = threadIdx.x >> 5;
    int n0 = blockIdx.y * 64 + tx * 2;
    size_t base = (size_t)blockIdx.x * 512 * NN + n0;
    __shared__ float2 red[8][33];

    uint32_t vals[64];
    float2 mx = { -1e30f, -1e30f };
    #pragma unroll 8
    for (int c = 0; c < 64; c++) {
        __nv_bfloat162 v = *(const __nv_bfloat162*)(P + base + (size_t)(ty * 64 + c) * NN);
        vals[c] = *(uint32_t*)&v;
        float2 f = __bfloat1622float2(v);
        mx.x = fmaxf(mx.x, f.x); mx.y = fmaxf(mx.y, f.y);
    }
    red[ty][tx] = mx;
    __syncthreads();
    float2 m = red[0][tx];
    #pragma unroll
    for (int g = 1; g < 8; g++) {
        m.x = fmaxf(m.x, red[g][tx].x);
        m.y = fmaxf(m.y, red[g][tx].y);
    }
    __syncthreads();

    float2 sum = { 0.f, 0.f };
    #pragma unroll 8
    for (int c = 0; c < 64; c++) {
        float2 f = __bfloat1622float2(*(__nv_bfloat162*)&vals[c]);
        float e0 = __expf(f.x - m.x), e1 = __expf(f.y - m.y);
        sum.x += e0; sum.y += e1;
        __nv_bfloat162 e = __floats2bfloat162_rn(e0, e1);
        vals[c] = *(uint32_t*)&e;
    }
    red[ty][tx] = sum;
    __syncthreads();
    float2 s = red[0][tx];
    #pragma unroll
    for (int g = 1; g < 8; g++) { s.x += red[g][tx].x; s.y += red[g][tx].y; }
    float2 inv = { 1.f / s.x, 1.f / s.y };

    #pragma unroll 8
    for (int c = 0; c < 64; c++) {
        float2 f = __bfloat1622float2(*(__nv_bfloat162*)&vals[c]);
        *(__nv_bfloat162*)(P + base + (size_t)(ty * 64 + c) * NN) =
            __floats2bfloat162_rn(f.x * inv.x, f.y * inv.y);
    }
}

// ---------------- tensor-core outer reduce ------------------------------------
template<int MR>
__global__ __launch_bounds__(256) void outer_mma_k(
    const bf16* __restrict__ A, int aC, int aH,
    const bf16* __restrict__ Rm, float* __restrict__ out)
{
    constexpr int AROWS = MR * 16;
    __shared__ bf16 sA[AROWS * 72];
    __shared__ bf16 sR[64 * 72];
    int bh = blockIdx.x, b = bh >> 3, h = bh & 7;
    const bf16* Ab = A  + ((size_t)b * aC  + h * aH) * NN;
    const bf16* Rb = Rm + ((size_t)b * 512 + h * 64) * NN;
    float* ob = out + (size_t)bh * (AROWS * 64);
    int tid = threadIdx.x, warp = tid >> 5, lane = tid & 31;

    float acc[MR][4];
    #pragma unroll
    for (int i = 0; i < MR; i++)
        #pragma unroll
        for (int j = 0; j < 4; j++) acc[i][j] = 0.f;

    int kbase = blockIdx.y * 1024;
    for (int kb = 0; kb < 16; kb++) {
        int k0 = kbase + kb * 64;
        #pragma unroll
        for (int c = tid; c < AROWS * 8; c += 256) {
            int r = c >> 3, cc = (c & 7) * 8;
            cpasync16(s2u(&sA[r * 72 + cc]), Ab + (size_t)r * NN + k0 + cc);
        }
        #pragma unroll
        for (int c = tid; c < 512; c += 256) {
            int r = c >> 3, cc = (c & 7) * 8;
            cpasync16(s2u(&sR[r * 72 + cc]), Rb + (size_t)r * NN + k0 + cc);
        }
        cp_commit(); cp_wait0();
        __syncthreads();

        int r0 = warp * 8;
        #pragma unroll
        for (int ks = 0; ks < 4; ks++) {
            uint32_t a[MR][4];
            #pragma unroll
            for (int mt = 0; mt < MR; mt++)
                ldsm4(a[mt][0], a[mt][1], a[mt][2], a[mt][3],
                      s2u(&sA[(mt * 16 + (lane & 15)) * 72 + ks * 16 + (lane >> 4) * 8]));
            uint32_t b0, b1;
            {
                int j = lane & 7, half = (lane >> 3) & 1;
                ldsm2(b0, b1, s2u(&sR[(r0 + j) * 72 + ks * 16 + half * 8]));
            }
            #pragma unroll
            for (int mt = 0; mt < MR; mt++)
                mma16816(acc[mt], a[mt], b0, b1);
        }
        __syncthreads();
    }

    int row = lane >> 2, col = warp * 8 + (lane & 3) * 2;
    #pragma unroll
    for (int mt = 0; mt < MR; mt++) {
        atomicAdd(&ob[(mt * 16 + row)     * 64 + col],     acc[mt][0]);
        atomicAdd(&ob[(mt * 16 + row)     * 64 + col + 1], acc[mt][1]);
        atomicAdd(&ob[(mt * 16 + row + 8) * 64 + col],     acc[mt][2]);
        atomicAdd(&ob[(mt * 16 + row + 8) * 64 + col + 1], acc[mt][3]);
    }
}

// ---------------- tiny attention per (b,h) ------------------------------------
__global__ __launch_bounds__(64) void attn_k(
    const float* __restrict__ qr, const float* __restrict__ krvr,
    float* __restrict__ vals)
{
    int bh = blockIdx.x; int t = threadIdx.x;
    __shared__ float sq[2048], sk[2048], sv[2048];
    const float* pq = qr   + (size_t)bh * 2048;
    const float* pk = krvr + (size_t)bh * 4096;
    const float* pv = pk + 2048;
    for (int i = t; i < 2048; i += 64) { sq[i] = pq[i]; sk[i] = pk[i]; sv[i] = pv[i]; }
    __syncthreads();

    float sc[64];
    #pragma unroll 4
    for (int k = 0; k < 64; k++) {
        float s = 0.f;
        #pragma unroll
        for (int d = 0; d < 32; d++) s += sq[d * 64 + t] * sk[d * 64 + k];
        sc[k] = s * 0.17677669529663687f;
    }
    float m = -1e30f;
    #pragma unroll
    for (int k = 0; k < 64; k++) m = fmaxf(m, sc[k]);
    float s = 0.f;
    #pragma unroll
    for (int k = 0; k < 64; k++) { sc[k] = __expf(sc[k] - m); s += sc[k]; }
    float inv = 1.f / s;
    #pragma unroll
    for (int k = 0; k < 64; k++) sc[k] *= inv;

    #pragma unroll 4
    for (int d = 0; d < 32; d++) {
        float v = 0.f;
        #pragma unroll
        for (int k = 0; k < 64; k++) v += sv[d * 64 + k] * sc[k];
        vals[(size_t)bh * 2048 + d * 64 + t] = v;
    }
}

// ---------------- U[b][m][h*64+r] = sum_d Wout[m][h*32+d] * vals[bh][d][r] ----
__global__ __launch_bounds__(256) void u_k(
    const float* __restrict__ Wout, const float* __restrict__ vals,
    bf16* __restrict__ U)
{
    int bh = blockIdx.x, b = bh >> 3, h = bh & 7;
    int m = threadIdx.x;
    __shared__ float vs[2048];
    const float* pv = vals + (size_t)bh * 2048;
    for (int i = threadIdx.x; i < 2048; i += 256) vs[i] = pv[i];
    __syncthreads();

    float acc[64];
    #pragma unroll
    for (int r = 0; r < 64; r++) acc[r] = 0.f;
    #pragma unroll 4
    for (int d = 0; d < 32; d++) {
        float w = Wout[(size_t)m * 256 + h * 32 + d];
        #pragma unroll
        for (int r = 0; r < 64; r++) acc[r] += w * vs[d * 64 + r];
    }
    bf16* up = U + ((size_t)b * 256 + m) * 512 + h * 64;
    #pragma unroll
    for (int r = 0; r < 32; r++) {
        __nv_bfloat162 o = { __float2bfloat16(acc[r * 2]), __float2bfloat16(acc[r * 2 + 1]) };
        *(__nv_bfloat162*)(up + r * 2) = o;
    }
}

// ------------------------------ launcher --------------------------------------
extern "C" void kernel_launch(void* const* d_in, const int* in_sizes, int n_in,
                              void* d_out, int out_size)
{
    const float* src   = (const float*)d_in[0];
    const float* tgt   = (const float*)d_in[1];
    const float* Wq    = (const float*)d_in[2];
    const float* bq    = (const float*)d_in[3];
    const float* Wkv   = (const float*)d_in[4];
    const float* bkv   = (const float*)d_in[5];
    const float* Wrq   = (const float*)d_in[6];
    const float* brq   = (const float*)d_in[7];
    const float* Wrk   = (const float*)d_in[8];
    const float* brk   = (const float*)d_in[9];
    const float* Wout  = (const float*)d_in[10];
    const float* bout  = (const float*)d_in[11];
    const float* alpha = (const float*)d_in[12];
    float* out = (float*)d_out;

    bf16 *pq, *pkv, *pRq, *pRk, *psrcb, *ptgtb, *pWq, *pWkv, *pWrq, *pWrk, *pU;
    float *pqr, *pkrvr, *pvals;
    cudaGetSymbolAddress((void**)&pq,    g_q);
    cudaGetSymbolAddress((void**)&pkv,   g_kv);
    cudaGetSymbolAddress((void**)&pRq,   g_Rq);
    cudaGetSymbolAddress((void**)&pRk,   g_Rk);
    cudaGetSymbolAddress((void**)&psrcb, g_srcb);
    cudaGetSymbolAddress((void**)&ptgtb, g_tgtb);
    cudaGetSymbolAddress((void**)&pWq,   g_Wqb);
    cudaGetSymbolAddress((void**)&pWkv,  g_Wkvb);
    cudaGetSymbolAddress((void**)&pWrq,  g_Wrqb);
    cudaGetSymbolAddress((void**)&pWrk,  g_Wrkb);
    cudaGetSymbolAddress((void**)&pU,    g_U);
    cudaGetSymbolAddress((void**)&pqr,   g_qr);
    cudaGetSymbolAddress((void**)&pkrvr, g_krvr);
    cudaGetSymbolAddress((void**)&pvals, g_vals);

    cudaFuncSetAttribute(hgemm_k, cudaFuncAttributeMaxDynamicSharedMemorySize, HSMEM_BYTES);

    {
        long long total = (long long)C_SRC + C_TGT + C_WQ + C_WKV + C_WR + C_WR + C_Z;
        int blocks = (int)((total + 255) / 256);
        prep_k<<<blocks, 256>>>(src, tgt, Wq, Wkv, Wrq, Wrk,
                                psrcb, ptgtb, pWq, pWkv, pWrq, pWrk, pqr, pkrvr);
    }

    const dim3 gB (NN / 128, 2, BB);   // M=256
    const dim3 gB2(NN / 128, 4, BB);   // M=512

    hgemm_k<<<gB2, 256, HSMEM_BYTES>>>(pWkv, bkv, psrcb, pkv, nullptr, 512, 256, 0, 0, nullptr, nullptr);
    hgemm_k<<<gB2, 256, HSMEM_BYTES>>>(pWrq, brq, ptgtb, pRq, nullptr, 512, 256, 0, 0, nullptr, nullptr);
    hgemm_k<<<gB2, 256, HSMEM_BYTES>>>(pWrk, brk, psrcb, pRk, nullptr, 512, 256, 0, 0, nullptr, nullptr);

    softmax1p_k<<<dim3(BB, NN / 64), 256>>>(pRq);
    hgemm_k<<<gB, 256, HSMEM_BYTES>>>(pWq, bq, ptgtb, pq, nullptr, 256, 256, 0, 0, nullptr, nullptr);  // profiled slot
    softmax1p_k<<<dim3(BB, NN / 64), 256>>>(pRk);

    outer_mma_k<2><<<dim3(64, 9), 256>>>(pq,  256, 32, pRq, pqr);
    outer_mma_k<4><<<dim3(64, 9), 256>>>(pkv, 512, 64, pRk, pkrvr);

    attn_k<<<64, 64>>>(pqr, pkrvr, pvals);

    u_k<<<64, 256>>>(Wout, pvals, pU);

    hgemm_k<<<gB, 256, HSMEM_BYTES>>>(pU, bout, pRq, nullptr, out, 256, 512, 1, 1, tgt, alpha);
}